// round 6
// baseline (speedup 1.0000x reference)
#include <cuda_runtime.h>
#include <cuda_bf16.h>
#include <math.h>
#include <stdint.h>

// Problem constants
#define SEQ 2048
#define BATCH 2
#define EMB 1024
#define HEADS 16
#define HDIM 64
#define ROWS (SEQ * BATCH)   // 4096

// ---------------------------------------------------------------------------
// Scratch (__device__ globals: allocation-free rule)
// ---------------------------------------------------------------------------
__device__ __align__(16) __nv_bfloat16 g_xn_hi[(size_t)ROWS * EMB];
__device__ __align__(16) __nv_bfloat16 g_xn_lo[(size_t)ROWS * EMB];
__device__ __align__(16) __nv_bfloat16 g_inw_hi[(size_t)2 * EMB * EMB];
__device__ __align__(16) __nv_bfloat16 g_inw_lo[(size_t)2 * EMB * EMB];
__device__ __align__(16) __nv_bfloat16 g_ow_hi[(size_t)EMB * EMB];
__device__ __align__(16) __nv_bfloat16 g_ow_lo[(size_t)EMB * EMB];
__device__ __align__(16) __nv_bfloat16 g_gt_hi[(size_t)ROWS * EMB];
__device__ __align__(16) __nv_bfloat16 g_gt_lo[(size_t)ROWS * EMB];
// qkv in head-major split-bf16: [(b*16+h)][s][d]
__device__ __align__(16) __nv_bfloat16 g_k_hi[(size_t)ROWS * EMB];
__device__ __align__(16) __nv_bfloat16 g_k_lo[(size_t)ROWS * EMB];
__device__ float g_u[(size_t)ROWS * EMB];

__device__ __forceinline__ float silu_f(float x) {
    return x / (1.0f + expf(-x));
}

__device__ __forceinline__ uint32_t smem_u32(const void* p) {
    uint32_t a;
    asm("{ .reg .u64 t; cvta.to.shared.u64 t, %1; cvt.u32.u64 %0, t; }" : "=r"(a) : "l"(p));
    return a;
}

// Portable async-copy / ldmatrix / mma (compute_103-safe, sm_80+ ISA)
#define CP16(dst_u32, src_gptr) \
    asm volatile("cp.async.cg.shared.global [%0], [%1], 16;" \
                 :: "r"(dst_u32), "l"(__cvta_generic_to_global(src_gptr)) : "memory")
#define CP_COMMIT() asm volatile("cp.async.commit_group;" ::: "memory")
#define CP_WAIT(N)  asm volatile("cp.async.wait_group %0;" :: "n"(N) : "memory")

__device__ __forceinline__ void ldsm4(uint32_t* r, uint32_t addr) {
    asm volatile("ldmatrix.sync.aligned.m8n8.x4.shared.b16 {%0,%1,%2,%3}, [%4];"
                 : "=r"(r[0]), "=r"(r[1]), "=r"(r[2]), "=r"(r[3]) : "r"(addr));
}
__device__ __forceinline__ void ldsm4t(uint32_t* r, uint32_t addr) {
    asm volatile("ldmatrix.sync.aligned.m8n8.x4.trans.shared.b16 {%0,%1,%2,%3}, [%4];"
                 : "=r"(r[0]), "=r"(r[1]), "=r"(r[2]), "=r"(r[3]) : "r"(addr));
}
__device__ __forceinline__ void mma16816(float* c, const uint32_t* a,
                                         uint32_t b0, uint32_t b1) {
    asm volatile(
        "mma.sync.aligned.m16n8k16.row.col.f32.bf16.bf16.f32 "
        "{%0,%1,%2,%3}, {%4,%5,%6,%7}, {%8,%9}, {%0,%1,%2,%3};"
        : "+f"(c[0]), "+f"(c[1]), "+f"(c[2]), "+f"(c[3])
        : "r"(a[0]), "r"(a[1]), "r"(a[2]), "r"(a[3]), "r"(b0), "r"(b1));
}

__device__ __forceinline__ void split_bf16(float v, __nv_bfloat16& hi, __nv_bfloat16& lo) {
    hi = __float2bfloat16(v);
    lo = __float2bfloat16(v - __bfloat162float(hi));
}
// split two floats -> packed hi pair + lo pair (bf16x2 as uint32)
__device__ __forceinline__ void split2(float f0, float f1, uint32_t& hi, uint32_t& lo) {
    __nv_bfloat16 h0 = __float2bfloat16(f0);
    __nv_bfloat16 h1 = __float2bfloat16(f1);
    __nv_bfloat16 l0 = __float2bfloat16(f0 - __bfloat162float(h0));
    __nv_bfloat16 l1 = __float2bfloat16(f1 - __bfloat162float(h1));
    __nv_bfloat162 H = __halves2bfloat162(h0, h1);
    __nv_bfloat162 L = __halves2bfloat162(l0, l1);
    hi = *reinterpret_cast<uint32_t*>(&H);
    lo = *reinterpret_cast<uint32_t*>(&L);
}

// ---------------------------------------------------------------------------
// Kernel 1: LayerNorm -> split-bf16 xnorm. One block (256 thr) per row.
// ---------------------------------------------------------------------------
__global__ void ln_kernel(const float* __restrict__ src,
                          const float* __restrict__ gamma,
                          const float* __restrict__ beta) {
    int row = blockIdx.x;
    int t = threadIdx.x;
    const float4* x4 = (const float4*)(src + (size_t)row * EMB);
    float4 v = x4[t];
    float s = v.x + v.y + v.z + v.w;
    float q = v.x * v.x + v.y * v.y + v.z * v.z + v.w * v.w;
    #pragma unroll
    for (int o = 16; o > 0; o >>= 1) {
        s += __shfl_xor_sync(0xFFFFFFFFu, s, o);
        q += __shfl_xor_sync(0xFFFFFFFFu, q, o);
    }
    __shared__ float ss[8], sq[8];
    int w = t >> 5, l = t & 31;
    if (l == 0) { ss[w] = s; sq[w] = q; }
    __syncthreads();
    float st = 0.f, qt = 0.f;
    #pragma unroll
    for (int i = 0; i < 8; i++) { st += ss[i]; qt += sq[i]; }
    float mu = st * (1.0f / EMB);
    float var = qt * (1.0f / EMB) - mu * mu;
    float inv = rsqrtf(var + 1e-5f);
    float4 gg = ((const float4*)gamma)[t];
    float4 bb = ((const float4*)beta)[t];
    float o[4];
    o[0] = (v.x - mu) * inv * gg.x + bb.x;
    o[1] = (v.y - mu) * inv * gg.y + bb.y;
    o[2] = (v.z - mu) * inv * gg.z + bb.z;
    o[3] = (v.w - mu) * inv * gg.w + bb.w;
    size_t base = (size_t)row * EMB + t * 4;
    #pragma unroll
    for (int e = 0; e < 4; e++) {
        __nv_bfloat16 hi, lo;
        split_bf16(o[e], hi, lo);
        g_xn_hi[base + e] = hi;
        g_xn_lo[base + e] = lo;
    }
}

// ---------------------------------------------------------------------------
// Kernel 2: convert in_proj_w + out_proj_w fp32 -> split bf16
// ---------------------------------------------------------------------------
__global__ void wconv_kernel(const float* __restrict__ inw,
                             const float* __restrict__ outw) {
    const size_t N1 = (size_t)2 * EMB * EMB / 4;
    const size_t N2 = (size_t)EMB * EMB / 4;
    size_t i = (size_t)blockIdx.x * blockDim.x + threadIdx.x;
    if (i < N1) {
        float4 v = ((const float4*)inw)[i];
        float f[4] = {v.x, v.y, v.z, v.w};
        #pragma unroll
        for (int e = 0; e < 4; e++) {
            __nv_bfloat16 hi, lo;
            split_bf16(f[e], hi, lo);
            g_inw_hi[i * 4 + e] = hi;
            g_inw_lo[i * 4 + e] = lo;
        }
    } else if (i < N1 + N2) {
        size_t j = i - N1;
        float4 v = ((const float4*)outw)[j];
        float f[4] = {v.x, v.y, v.z, v.w};
        #pragma unroll
        for (int e = 0; e < 4; e++) {
            __nv_bfloat16 hi, lo;
            split_bf16(f[e], hi, lo);
            g_ow_hi[j * 4 + e] = hi;
            g_ow_lo[j * 4 + e] = lo;
        }
    }
}

// ---------------------------------------------------------------------------
// Split-bf16 GEMM via mma.sync:  C[M,N] = A[M,K] @ B[N,K]^T   (3-pass split)
// Block 128x128, BK=32, 8 warps (warp tile 32x64), 4-stage cp.async pipeline.
// MODE 0 = in_proj (bias+silu -> qkv split-bf16 head-major / u fp32)
// MODE 1 = out_proj (src+bias -> out)
// ---------------------------------------------------------------------------
#define BK 32
#define NKS (EMB / BK)          // 32
#define STG_BYTES 32768
#define SUB_A_HI 0
#define SUB_A_LO 8192
#define SUB_B_HI 16384
#define SUB_B_LO 24576
#define GEMM_SMEM (4 * STG_BYTES)   // 131072

__device__ __forceinline__ void stage_load(uint32_t sdst,
                                           const __nv_bfloat16* __restrict__ Ahi,
                                           const __nv_bfloat16* __restrict__ Alo,
                                           const __nv_bfloat16* __restrict__ Bhi,
                                           const __nv_bfloat16* __restrict__ Blo,
                                           int bm, int bn, int k0, int tid) {
    #pragma unroll
    for (int t = 0; t < 2; t++) {
        int idx = tid + t * 256;            // 0..511
        int row = idx >> 2, seg = idx & 3;  // 128 rows x 4 x 16B
        uint32_t soff = row * 64 + ((seg ^ ((row >> 1) & 3)) << 4);
        size_t ga = (size_t)(bm + row) * EMB + k0 + seg * 8;
        size_t gb = (size_t)(bn + row) * EMB + k0 + seg * 8;
        CP16(sdst + SUB_A_HI + soff, Ahi + ga);
        CP16(sdst + SUB_A_LO + soff, Alo + ga);
        CP16(sdst + SUB_B_HI + soff, Bhi + gb);
        CP16(sdst + SUB_B_LO + soff, Blo + gb);
    }
}

template <int MODE>
__global__ __launch_bounds__(256, 1)
void gemm_mma_kernel(const float* __restrict__ bias,
                     const float* __restrict__ src,
                     float* __restrict__ out) {
    extern __shared__ char smem[];
    uint32_t sb = smem_u32(smem);
    int tid = threadIdx.x, warp = tid >> 5, lane = tid & 31;
    int bn = blockIdx.x * 128, bm = blockIdx.y * 128;

    const __nv_bfloat16 *Ahi, *Alo, *Bhi, *Blo;
    if (MODE == 0) { Ahi = g_xn_hi; Alo = g_xn_lo; Bhi = g_inw_hi; Blo = g_inw_lo; }
    else           { Ahi = g_gt_hi; Alo = g_gt_lo; Bhi = g_ow_hi;  Blo = g_ow_lo; }

    #pragma unroll
    for (int s = 0; s < 3; s++) {
        stage_load(sb + s * STG_BYTES, Ahi, Alo, Bhi, Blo, bm, bn, s * BK, tid);
        CP_COMMIT();
    }

    int wm = (warp >> 1) * 32;
    int wn = (warp & 1) * 64;
    int lrow = lane & 15;
    int lseg = lane >> 4;

    float acc[2][8][4];
    #pragma unroll
    for (int a = 0; a < 2; a++)
        #pragma unroll
        for (int b = 0; b < 8; b++)
            #pragma unroll
            for (int c = 0; c < 4; c++) acc[a][b][c] = 0.f;

    for (int kt = 0; kt < NKS; kt++) {
        CP_WAIT(2);
        __syncthreads();
        uint32_t st = sb + (kt & 3) * STG_BYTES;
        if (kt + 3 < NKS) {
            stage_load(sb + ((kt + 3) & 3) * STG_BYTES, Ahi, Alo, Bhi, Blo,
                       bm, bn, (kt + 3) * BK, tid);
            CP_COMMIT();
        }
        #pragma unroll
        for (int kk = 0; kk < 2; kk++) {
            int seg = kk * 2 + lseg;
            uint32_t ahi[2][4], alo[2][4];
            #pragma unroll
            for (int mt = 0; mt < 2; mt++) {
                int r = wm + mt * 16 + lrow;
                uint32_t off = r * 64 + ((seg ^ ((r >> 1) & 3)) << 4);
                ldsm4(ahi[mt], st + SUB_A_HI + off);
                ldsm4(alo[mt], st + SUB_A_LO + off);
            }
            uint32_t bhi[4][4], blo[4][4];
            #pragma unroll
            for (int p = 0; p < 4; p++) {
                int r = wn + p * 16 + lrow;
                uint32_t off = r * 64 + ((seg ^ ((r >> 1) & 3)) << 4);
                ldsm4(bhi[p], st + SUB_B_HI + off);
                ldsm4(blo[p], st + SUB_B_LO + off);
            }
            #pragma unroll
            for (int mt = 0; mt < 2; mt++)
                #pragma unroll
                for (int p = 0; p < 4; p++) {
                    mma16816(acc[mt][2 * p],     ahi[mt], bhi[p][0], bhi[p][2]);
                    mma16816(acc[mt][2 * p],     ahi[mt], blo[p][0], blo[p][2]);
                    mma16816(acc[mt][2 * p],     alo[mt], bhi[p][0], bhi[p][2]);
                    mma16816(acc[mt][2 * p + 1], ahi[mt], bhi[p][1], bhi[p][3]);
                    mma16816(acc[mt][2 * p + 1], ahi[mt], blo[p][1], blo[p][3]);
                    mma16816(acc[mt][2 * p + 1], alo[mt], bhi[p][1], bhi[p][3]);
                }
        }
    }

    int r0 = bm + wm + (lane >> 2);
    int c0 = bn + wn + 2 * (lane & 3);
    #pragma unroll
    for (int mt = 0; mt < 2; mt++) {
        #pragma unroll
        for (int nt = 0; nt < 8; nt++) {
            int col = c0 + nt * 8;
            float* a = acc[mt][nt];
            int r = r0 + mt * 16;
            if (MODE == 0) {
                float b0 = bias[col], b1 = bias[col + 1];
                float v0 = silu_f(a[0] + b0);
                float v1 = silu_f(a[1] + b1);
                float v2 = silu_f(a[2] + b0);
                float v3 = silu_f(a[3] + b1);
                if (bn < EMB) {
                    // qkv half -> split-bf16 head-major [(b*16+h)][s][d]
                    int h = col >> 6, d = col & 63;
                    int s1 = r >> 1, bb = r & 1;
                    size_t ix1 = ((size_t)((bb << 4) + h) * SEQ + s1) * HDIM + d;
                    size_t ix2 = ((size_t)((bb << 4) + h) * SEQ + s1 + 4) * HDIM + d;
                    uint32_t hi, lo;
                    split2(v0, v1, hi, lo);
                    *(uint32_t*)((char*)g_k_hi + ix1 * 2) = hi;
                    *(uint32_t*)((char*)g_k_lo + ix1 * 2) = lo;
                    split2(v2, v3, hi, lo);
                    *(uint32_t*)((char*)g_k_hi + ix2 * 2) = hi;
                    *(uint32_t*)((char*)g_k_lo + ix2 * 2) = lo;
                } else {
                    int cc = col - EMB;
                    *(float2*)&g_u[(size_t)r * EMB + cc]       = make_float2(v0, v1);
                    *(float2*)&g_u[(size_t)(r + 8) * EMB + cc] = make_float2(v2, v3);
                }
            } else {
                float b0 = bias[col], b1 = bias[col + 1];
                float2 s0 = *(const float2*)&src[(size_t)r * EMB + col];
                float2 s1 = *(const float2*)&src[(size_t)(r + 8) * EMB + col];
                *(float2*)&out[(size_t)r * EMB + col] =
                    make_float2(s0.x + a[0] + b0, s0.y + a[1] + b1);
                *(float2*)&out[(size_t)(r + 8) * EMB + col] =
                    make_float2(s1.x + a[2] + b0, s1.y + a[3] + b1);
            }
        }
    }
}

// ---------------------------------------------------------------------------
// Kernel 3: tensor-core causal SiLU-attention, fused gating epilogue.
// Block = 128 q-rows x one (b,h). 8 warps, warp = 16 q-rows.
// K/V tiles (same data) of 64 keys, double-buffered cp.async.
// ---------------------------------------------------------------------------
#define ATT_SM_Q 0            // Qhi 16K | Qlo 16K
#define ATT_SM_K 32768        // 2 buffers x (Khi 8K | Klo 8K)
#define ATT_KBUF 16384
#define ATT_SMEM 65536

__device__ __forceinline__ void att_load_k(uint32_t sdst,
                                           const __nv_bfloat16* __restrict__ Khi,
                                           const __nv_bfloat16* __restrict__ Klo,
                                           int k0, int tid) {
    #pragma unroll
    for (int t = 0; t < 2; t++) {
        int idx = tid + t * 256;            // 0..511 -> 64 rows x 8 segs
        int row = idx >> 3, seg = idx & 7;
        uint32_t soff = row * 128 + ((seg ^ (row & 7)) << 4);
        size_t g = (size_t)(k0 + row) * HDIM + seg * 8;
        CP16(sdst + soff, Khi + g);
        CP16(sdst + 8192 + soff, Klo + g);
    }
}

__global__ __launch_bounds__(256, 1) void attn_kernel() {
    extern __shared__ char smem[];
    uint32_t sb = smem_u32(smem);
    int tid = threadIdx.x, warp = tid >> 5, lane = tid & 31;
    int qb = blockIdx.x;      // 0..15 (128 q rows each)
    int kvb = blockIdx.y;     // 0..31 = b*16 + h
    int b = kvb >> 4, h = kvb & 15;
    const __nv_bfloat16* Khi = g_k_hi + (size_t)kvb * SEQ * HDIM;
    const __nv_bfloat16* Klo = g_k_lo + (size_t)kvb * SEQ * HDIM;

    int L = 2 * qb + 1;       // last k-tile index (inclusive)

    // Prologue: stage Q (128 rows) + K tiles 0,1
    #pragma unroll
    for (int t = 0; t < 4; t++) {
        int idx = tid + t * 256;            // 0..1023 -> 128 rows x 8 segs
        int row = idx >> 3, seg = idx & 7;
        uint32_t soff = row * 128 + ((seg ^ (row & 7)) << 4);
        size_t g = (size_t)(qb * 128 + row) * HDIM + seg * 8;
        CP16(sb + ATT_SM_Q + soff, Khi + g);
        CP16(sb + ATT_SM_Q + 16384 + soff, Klo + g);
    }
    att_load_k(sb + ATT_SM_K, Khi, Klo, 0, tid);
    CP_COMMIT();                                   // G0: Q + K0
    att_load_k(sb + ATT_SM_K + ATT_KBUF, Khi, Klo, 64, tid);
    CP_COMMIT();                                   // G1: K1
    CP_WAIT(1);
    __syncthreads();

    // Q fragments (A-operand, m16k16 x 4 k-steps), hi+lo
    uint32_t qhi[4][4], qlo[4][4];
    #pragma unroll
    for (int ks = 0; ks < 4; ks++) {
        int r = warp * 16 + (lane & 15);
        uint32_t soff = r * 128 + ((((ks * 2 + (lane >> 4))) ^ (r & 7)) << 4);
        ldsm4(qhi[ks], sb + ATT_SM_Q + soff);
        ldsm4(qlo[ks], sb + ATT_SM_Q + 16384 + soff);
    }

    float oacc[8][4];
    #pragma unroll
    for (int i = 0; i < 8; i++)
        #pragma unroll
        for (int c = 0; c < 4; c++) oacc[i][c] = 0.f;

    for (int kt = 0; kt <= L; kt++) {
        uint32_t sK = sb + ATT_SM_K + (uint32_t)(kt & 1) * ATT_KBUF;
        bool active = (kt * 64 <= qb * 128 + warp * 16 + 15);
        if (active) {
            // ---- scores: S = Q @ K^T (3-pass split) ----
            float sacc[8][4];
            #pragma unroll
            for (int i = 0; i < 8; i++)
                #pragma unroll
                for (int c = 0; c < 4; c++) sacc[i][c] = 0.f;
            #pragma unroll
            for (int ks = 0; ks < 4; ks++) {
                #pragma unroll
                for (int p = 0; p < 4; p++) {
                    int r = p * 16 + (lane & 15);
                    uint32_t off = r * 128 + ((((ks * 2 + (lane >> 4))) ^ (r & 7)) << 4);
                    uint32_t kh[4], kl[4];
                    ldsm4(kh, sK + off);
                    ldsm4(kl, sK + 8192 + off);
                    mma16816(sacc[2 * p],     qhi[ks], kh[0], kh[2]);
                    mma16816(sacc[2 * p],     qhi[ks], kl[0], kl[2]);
                    mma16816(sacc[2 * p],     qlo[ks], kh[0], kh[2]);
                    mma16816(sacc[2 * p + 1], qhi[ks], kh[1], kh[3]);
                    mma16816(sacc[2 * p + 1], qhi[ks], kl[1], kl[3]);
                    mma16816(sacc[2 * p + 1], qlo[ks], kh[1], kh[3]);
                }
            }
            // ---- scale + silu + causal mask ----
            bool need_mask = (kt * 64 + 63 > qb * 128 + warp * 16);
            int qrow0 = qb * 128 + warp * 16 + (lane >> 2);
            #pragma unroll
            for (int nt = 0; nt < 8; nt++) {
                int kcol0 = kt * 64 + nt * 8 + 2 * (lane & 3);
                #pragma unroll
                for (int c = 0; c < 4; c++) {
                    float w = silu_f(sacc[nt][c] * 0.125f);
                    if (need_mask) {
                        int q = qrow0 + ((c >= 2) ? 8 : 0);
                        int k = kcol0 + (c & 1);
                        if (k > q) w = 0.f;
                    }
                    sacc[nt][c] = w;
                }
            }
            // ---- W -> A-frags (hi/lo) for PV ----
            uint32_t ahi[4][4], alo[4][4];
            #pragma unroll
            for (int ks = 0; ks < 4; ks++) {
                split2(sacc[2 * ks][0],     sacc[2 * ks][1],     ahi[ks][0], alo[ks][0]);
                split2(sacc[2 * ks][2],     sacc[2 * ks][3],     ahi[ks][1], alo[ks][1]);
                split2(sacc[2 * ks + 1][0], sacc[2 * ks + 1][1], ahi[ks][2], alo[ks][2]);
                split2(sacc[2 * ks + 1][2], sacc[2 * ks + 1][3], ahi[ks][3], alo[ks][3]);
            }
            // ---- O += W @ V (V == K tile, trans-ldmatrix; 3-pass split) ----
            #pragma unroll
            for (int ks = 0; ks < 4; ks++) {
                #pragma unroll
                for (int p = 0; p < 4; p++) {
                    int r = ks * 16 + (lane & 15);
                    uint32_t off = r * 128 + ((((p * 2 + (lane >> 4))) ^ (r & 7)) << 4);
                    uint32_t vh[4], vl[4];
                    ldsm4t(vh, sK + off);
                    ldsm4t(vl, sK + 8192 + off);
                    mma16816(oacc[2 * p],     ahi[ks], vh[0], vh[1]);
                    mma16816(oacc[2 * p],     ahi[ks], vl[0], vl[1]);
                    mma16816(oacc[2 * p],     alo[ks], vh[0], vh[1]);
                    mma16816(oacc[2 * p + 1], ahi[ks], vh[2], vh[3]);
                    mma16816(oacc[2 * p + 1], ahi[ks], vl[2], vl[3]);
                    mma16816(oacc[2 * p + 1], alo[ks], vh[2], vh[3]);
                }
            }
        }
        __syncthreads();
        if (kt + 2 <= L) {
            att_load_k(sb + ATT_SM_K + (uint32_t)(kt & 1) * ATT_KBUF, Khi, Klo,
                       (kt + 2) * 64, tid);
            CP_COMMIT();
        }
        if (kt + 1 <= L) {
            if (kt + 2 <= L) { CP_WAIT(1); } else { CP_WAIT(0); }
            __syncthreads();
        }
    }

    // ---- Epilogue: gated = O * u -> split-bf16 for out_proj A ----
    int srow0 = qb * 128 + warp * 16 + (lane >> 2);
    int dp = 2 * (lane & 3);
    #pragma unroll
    for (int nt = 0; nt < 8; nt++) {
        int d = nt * 8 + dp;
        #pragma unroll
        for (int half = 0; half < 2; half++) {
            int s = srow0 + half * 8;
            size_t m = (size_t)s * BATCH + b;
            size_t ix = m * EMB + h * HDIM + d;
            float2 uv = *(const float2*)&g_u[ix];
            float f0 = oacc[nt][half * 2]     * uv.x;
            float f1 = oacc[nt][half * 2 + 1] * uv.y;
            uint32_t hi, lo;
            split2(f0, f1, hi, lo);
            *(uint32_t*)((char*)g_gt_hi + ix * 2) = hi;
            *(uint32_t*)((char*)g_gt_lo + ix * 2) = lo;
        }
    }
}

// ---------------------------------------------------------------------------
extern "C" void kernel_launch(void* const* d_in, const int* in_sizes, int n_in,
                              void* d_out, int out_size) {
    const float* src   = (const float*)d_in[0];
    // d_in[1] = src_mask (causal tril) — predicate computed directly
    const float* in_w  = (const float*)d_in[2];
    const float* in_b  = (const float*)d_in[3];
    const float* out_w = (const float*)d_in[4];
    const float* out_b = (const float*)d_in[5];
    const float* ln_g  = (const float*)d_in[6];
    const float* ln_b  = (const float*)d_in[7];
    float* out = (float*)d_out;

    cudaFuncSetAttribute(attn_kernel, cudaFuncAttributeMaxDynamicSharedMemorySize, ATT_SMEM);
    cudaFuncSetAttribute(gemm_mma_kernel<0>, cudaFuncAttributeMaxDynamicSharedMemorySize, GEMM_SMEM);
    cudaFuncSetAttribute(gemm_mma_kernel<1>, cudaFuncAttributeMaxDynamicSharedMemorySize, GEMM_SMEM);

    ln_kernel<<<ROWS, 256>>>(src, ln_g, ln_b);
    wconv_kernel<<<3072, 256>>>(in_w, out_w);
    gemm_mma_kernel<0><<<dim3(2 * EMB / 128, ROWS / 128), 256, GEMM_SMEM>>>(
        in_b, nullptr, nullptr);
    attn_kernel<<<dim3(SEQ / 128, BATCH * HEADS), 256, ATT_SMEM>>>();
    gemm_mma_kernel<1><<<dim3(EMB / 128, ROWS / 128), 256, GEMM_SMEM>>>(
        out_b, src, out);
}

// round 9
// speedup vs baseline: 1.9652x; 1.9652x over previous
#include <cuda_runtime.h>
#include <cuda_bf16.h>
#include <math.h>
#include <stdint.h>

// Problem constants
#define SEQ 2048
#define BATCH 2
#define EMB 1024
#define HEADS 16
#define HDIM 64
#define ROWS (SEQ * BATCH)   // 4096

// ---------------------------------------------------------------------------
// Scratch (__device__ globals: allocation-free rule)
// ---------------------------------------------------------------------------
__device__ __align__(16) __nv_bfloat16 g_xn_hi[(size_t)ROWS * EMB];
__device__ __align__(16) __nv_bfloat16 g_xn_lo[(size_t)ROWS * EMB];
__device__ __align__(16) __nv_bfloat16 g_inw_hi[(size_t)2 * EMB * EMB];
__device__ __align__(16) __nv_bfloat16 g_inw_lo[(size_t)2 * EMB * EMB];
__device__ __align__(16) __nv_bfloat16 g_ow_hi[(size_t)EMB * EMB];
__device__ __align__(16) __nv_bfloat16 g_ow_lo[(size_t)EMB * EMB];
__device__ __align__(16) __nv_bfloat16 g_gt_hi[(size_t)ROWS * EMB];
__device__ __align__(16) __nv_bfloat16 g_gt_lo[(size_t)ROWS * EMB];
// qkv split-bf16, row-major [s*B+b][E] (d-contiguous per head: col h*64+d)
__device__ __align__(16) __nv_bfloat16 g_k_hi[(size_t)ROWS * EMB];
__device__ __align__(16) __nv_bfloat16 g_k_lo[(size_t)ROWS * EMB];
__device__ float g_u[(size_t)ROWS * EMB];

__device__ __forceinline__ float silu_f(float x) {
    return x / (1.0f + expf(-x));
}

__device__ __forceinline__ uint32_t smem_u32(const void* p) {
    uint32_t a;
    asm("{ .reg .u64 t; cvta.to.shared.u64 t, %1; cvt.u32.u64 %0, t; }" : "=r"(a) : "l"(p));
    return a;
}

// Portable async-copy / ldmatrix / mma (compute_103-safe, sm_80+ ISA)
#define CP16(dst_u32, src_gptr) \
    asm volatile("cp.async.cg.shared.global [%0], [%1], 16;" \
                 :: "r"(dst_u32), "l"(__cvta_generic_to_global(src_gptr)) : "memory")
#define CP_COMMIT() asm volatile("cp.async.commit_group;" ::: "memory")
#define CP_WAIT(N)  asm volatile("cp.async.wait_group %0;" :: "n"(N) : "memory")

__device__ __forceinline__ void ldsm4(uint32_t* r, uint32_t addr) {
    asm volatile("ldmatrix.sync.aligned.m8n8.x4.shared.b16 {%0,%1,%2,%3}, [%4];"
                 : "=r"(r[0]), "=r"(r[1]), "=r"(r[2]), "=r"(r[3]) : "r"(addr));
}
__device__ __forceinline__ void ldsm4t(uint32_t* r, uint32_t addr) {
    asm volatile("ldmatrix.sync.aligned.m8n8.x4.trans.shared.b16 {%0,%1,%2,%3}, [%4];"
                 : "=r"(r[0]), "=r"(r[1]), "=r"(r[2]), "=r"(r[3]) : "r"(addr));
}
__device__ __forceinline__ void mma16816(float* c, const uint32_t* a,
                                         uint32_t b0, uint32_t b1) {
    asm volatile(
        "mma.sync.aligned.m16n8k16.row.col.f32.bf16.bf16.f32 "
        "{%0,%1,%2,%3}, {%4,%5,%6,%7}, {%8,%9}, {%0,%1,%2,%3};"
        : "+f"(c[0]), "+f"(c[1]), "+f"(c[2]), "+f"(c[3])
        : "r"(a[0]), "r"(a[1]), "r"(a[2]), "r"(a[3]), "r"(b0), "r"(b1));
}

__device__ __forceinline__ void split_bf16(float v, __nv_bfloat16& hi, __nv_bfloat16& lo) {
    hi = __float2bfloat16(v);
    lo = __float2bfloat16(v - __bfloat162float(hi));
}
// split two floats -> packed hi pair + lo pair (bf16x2 as uint32)
__device__ __forceinline__ void split2(float f0, float f1, uint32_t& hi, uint32_t& lo) {
    __nv_bfloat16 h0 = __float2bfloat16(f0);
    __nv_bfloat16 h1 = __float2bfloat16(f1);
    __nv_bfloat16 l0 = __float2bfloat16(f0 - __bfloat162float(h0));
    __nv_bfloat16 l1 = __float2bfloat16(f1 - __bfloat162float(h1));
    __nv_bfloat162 H = __halves2bfloat162(h0, h1);
    __nv_bfloat162 L = __halves2bfloat162(l0, l1);
    hi = *reinterpret_cast<uint32_t*>(&H);
    lo = *reinterpret_cast<uint32_t*>(&L);
}

// ---------------------------------------------------------------------------
// Kernel 1: LayerNorm -> split-bf16 xnorm. One block (256 thr) per row.
// ---------------------------------------------------------------------------
__global__ void ln_kernel(const float* __restrict__ src,
                          const float* __restrict__ gamma,
                          const float* __restrict__ beta) {
    int row = blockIdx.x;
    int t = threadIdx.x;
    const float4* x4 = (const float4*)(src + (size_t)row * EMB);
    float4 v = x4[t];
    float s = v.x + v.y + v.z + v.w;
    float q = v.x * v.x + v.y * v.y + v.z * v.z + v.w * v.w;
    #pragma unroll
    for (int o = 16; o > 0; o >>= 1) {
        s += __shfl_xor_sync(0xFFFFFFFFu, s, o);
        q += __shfl_xor_sync(0xFFFFFFFFu, q, o);
    }
    __shared__ float ss[8], sq[8];
    int w = t >> 5, l = t & 31;
    if (l == 0) { ss[w] = s; sq[w] = q; }
    __syncthreads();
    float st = 0.f, qt = 0.f;
    #pragma unroll
    for (int i = 0; i < 8; i++) { st += ss[i]; qt += sq[i]; }
    float mu = st * (1.0f / EMB);
    float var = qt * (1.0f / EMB) - mu * mu;
    float inv = rsqrtf(var + 1e-5f);
    float4 gg = ((const float4*)gamma)[t];
    float4 bb = ((const float4*)beta)[t];
    float o[4];
    o[0] = (v.x - mu) * inv * gg.x + bb.x;
    o[1] = (v.y - mu) * inv * gg.y + bb.y;
    o[2] = (v.z - mu) * inv * gg.z + bb.z;
    o[3] = (v.w - mu) * inv * gg.w + bb.w;
    size_t base = (size_t)row * EMB + t * 4;
    #pragma unroll
    for (int e = 0; e < 4; e++) {
        __nv_bfloat16 hi, lo;
        split_bf16(o[e], hi, lo);
        g_xn_hi[base + e] = hi;
        g_xn_lo[base + e] = lo;
    }
}

// ---------------------------------------------------------------------------
// Kernel 2: convert in_proj_w + out_proj_w fp32 -> split bf16
// ---------------------------------------------------------------------------
__global__ void wconv_kernel(const float* __restrict__ inw,
                             const float* __restrict__ outw) {
    const size_t N1 = (size_t)2 * EMB * EMB / 4;
    const size_t N2 = (size_t)EMB * EMB / 4;
    size_t i = (size_t)blockIdx.x * blockDim.x + threadIdx.x;
    if (i < N1) {
        float4 v = ((const float4*)inw)[i];
        float f[4] = {v.x, v.y, v.z, v.w};
        #pragma unroll
        for (int e = 0; e < 4; e++) {
            __nv_bfloat16 hi, lo;
            split_bf16(f[e], hi, lo);
            g_inw_hi[i * 4 + e] = hi;
            g_inw_lo[i * 4 + e] = lo;
        }
    } else if (i < N1 + N2) {
        size_t j = i - N1;
        float4 v = ((const float4*)outw)[j];
        float f[4] = {v.x, v.y, v.z, v.w};
        #pragma unroll
        for (int e = 0; e < 4; e++) {
            __nv_bfloat16 hi, lo;
            split_bf16(f[e], hi, lo);
            g_ow_hi[j * 4 + e] = hi;
            g_ow_lo[j * 4 + e] = lo;
        }
    }
}

// ---------------------------------------------------------------------------
// Split-bf16 GEMM via mma.sync:  C[M,N] = A[M,K] @ B[N,K]^T   (3-pass split)
// Block 128x128, BK=32, 8 warps (warp tile 32x64), 4-stage cp.async pipeline.
// MODE 0 = in_proj (bias+silu -> qkv split-bf16 row-major / u fp32)
// MODE 1 = out_proj (src+bias -> out)
// ---------------------------------------------------------------------------
#define BK 32
#define NKS (EMB / BK)          // 32
#define STG_BYTES 32768
#define SUB_A_HI 0
#define SUB_A_LO 8192
#define SUB_B_HI 16384
#define SUB_B_LO 24576
#define GEMM_SMEM (4 * STG_BYTES)   // 131072

__device__ __forceinline__ void stage_load(uint32_t sdst,
                                           const __nv_bfloat16* __restrict__ Ahi,
                                           const __nv_bfloat16* __restrict__ Alo,
                                           const __nv_bfloat16* __restrict__ Bhi,
                                           const __nv_bfloat16* __restrict__ Blo,
                                           int bm, int bn, int k0, int tid) {
    #pragma unroll
    for (int t = 0; t < 2; t++) {
        int idx = tid + t * 256;            // 0..511
        int row = idx >> 2, seg = idx & 3;  // 128 rows x 4 x 16B
        uint32_t soff = row * 64 + ((seg ^ ((row >> 1) & 3)) << 4);
        size_t ga = (size_t)(bm + row) * EMB + k0 + seg * 8;
        size_t gb = (size_t)(bn + row) * EMB + k0 + seg * 8;
        CP16(sdst + SUB_A_HI + soff, Ahi + ga);
        CP16(sdst + SUB_A_LO + soff, Alo + ga);
        CP16(sdst + SUB_B_HI + soff, Bhi + gb);
        CP16(sdst + SUB_B_LO + soff, Blo + gb);
    }
}

template <int MODE>
__global__ __launch_bounds__(256, 1)
void gemm_mma_kernel(const float* __restrict__ bias,
                     const float* __restrict__ src,
                     float* __restrict__ out) {
    extern __shared__ char smem[];
    uint32_t sb = smem_u32(smem);
    int tid = threadIdx.x, warp = tid >> 5, lane = tid & 31;
    int bn = blockIdx.x * 128, bm = blockIdx.y * 128;

    const __nv_bfloat16 *Ahi, *Alo, *Bhi, *Blo;
    if (MODE == 0) { Ahi = g_xn_hi; Alo = g_xn_lo; Bhi = g_inw_hi; Blo = g_inw_lo; }
    else           { Ahi = g_gt_hi; Alo = g_gt_lo; Bhi = g_ow_hi;  Blo = g_ow_lo; }

    #pragma unroll
    for (int s = 0; s < 3; s++) {
        stage_load(sb + s * STG_BYTES, Ahi, Alo, Bhi, Blo, bm, bn, s * BK, tid);
        CP_COMMIT();
    }

    int wm = (warp >> 1) * 32;
    int wn = (warp & 1) * 64;
    int lrow = lane & 15;
    int lseg = lane >> 4;

    float acc[2][8][4];
    #pragma unroll
    for (int a = 0; a < 2; a++)
        #pragma unroll
        for (int b = 0; b < 8; b++)
            #pragma unroll
            for (int c = 0; c < 4; c++) acc[a][b][c] = 0.f;

    for (int kt = 0; kt < NKS; kt++) {
        CP_WAIT(2);
        __syncthreads();
        uint32_t st = sb + (kt & 3) * STG_BYTES;
        if (kt + 3 < NKS) {
            stage_load(sb + ((kt + 3) & 3) * STG_BYTES, Ahi, Alo, Bhi, Blo,
                       bm, bn, (kt + 3) * BK, tid);
            CP_COMMIT();
        }
        #pragma unroll
        for (int kk = 0; kk < 2; kk++) {
            int seg = kk * 2 + lseg;
            uint32_t ahi[2][4], alo[2][4];
            #pragma unroll
            for (int mt = 0; mt < 2; mt++) {
                int r = wm + mt * 16 + lrow;
                uint32_t off = r * 64 + ((seg ^ ((r >> 1) & 3)) << 4);
                ldsm4(ahi[mt], st + SUB_A_HI + off);
                ldsm4(alo[mt], st + SUB_A_LO + off);
            }
            uint32_t bhi[4][4], blo[4][4];
            #pragma unroll
            for (int p = 0; p < 4; p++) {
                int r = wn + p * 16 + lrow;
                uint32_t off = r * 64 + ((seg ^ ((r >> 1) & 3)) << 4);
                ldsm4(bhi[p], st + SUB_B_HI + off);
                ldsm4(blo[p], st + SUB_B_LO + off);
            }
            #pragma unroll
            for (int mt = 0; mt < 2; mt++)
                #pragma unroll
                for (int p = 0; p < 4; p++) {
                    mma16816(acc[mt][2 * p],     ahi[mt], bhi[p][0], bhi[p][2]);
                    mma16816(acc[mt][2 * p],     ahi[mt], blo[p][0], blo[p][2]);
                    mma16816(acc[mt][2 * p],     alo[mt], bhi[p][0], bhi[p][2]);
                    mma16816(acc[mt][2 * p + 1], ahi[mt], bhi[p][1], bhi[p][3]);
                    mma16816(acc[mt][2 * p + 1], ahi[mt], blo[p][1], blo[p][3]);
                    mma16816(acc[mt][2 * p + 1], alo[mt], bhi[p][1], bhi[p][3]);
                }
        }
    }

    int r0 = bm + wm + (lane >> 2);
    int c0 = bn + wn + 2 * (lane & 3);
    #pragma unroll
    for (int mt = 0; mt < 2; mt++) {
        #pragma unroll
        for (int nt = 0; nt < 8; nt++) {
            int col = c0 + nt * 8;
            float* a = acc[mt][nt];
            int r = r0 + mt * 16;
            if (MODE == 0) {
                float b0 = bias[col], b1 = bias[col + 1];
                float v0 = silu_f(a[0] + b0);
                float v1 = silu_f(a[1] + b1);
                float v2 = silu_f(a[2] + b0);
                float v3 = silu_f(a[3] + b1);
                if (bn < EMB) {
                    // qkv half -> split-bf16, row-major (coalesced pair stores)
                    uint32_t hi, lo;
                    split2(v0, v1, hi, lo);
                    *(uint32_t*)((char*)g_k_hi + ((size_t)r * EMB + col) * 2) = hi;
                    *(uint32_t*)((char*)g_k_lo + ((size_t)r * EMB + col) * 2) = lo;
                    split2(v2, v3, hi, lo);
                    *(uint32_t*)((char*)g_k_hi + ((size_t)(r + 8) * EMB + col) * 2) = hi;
                    *(uint32_t*)((char*)g_k_lo + ((size_t)(r + 8) * EMB + col) * 2) = lo;
                } else {
                    int cc = col - EMB;
                    *(float2*)&g_u[(size_t)r * EMB + cc]       = make_float2(v0, v1);
                    *(float2*)&g_u[(size_t)(r + 8) * EMB + cc] = make_float2(v2, v3);
                }
            } else {
                float b0 = bias[col], b1 = bias[col + 1];
                float2 s0 = *(const float2*)&src[(size_t)r * EMB + col];
                float2 s1 = *(const float2*)&src[(size_t)(r + 8) * EMB + col];
                *(float2*)&out[(size_t)r * EMB + col] =
                    make_float2(s0.x + a[0] + b0, s0.y + a[1] + b1);
                *(float2*)&out[(size_t)(r + 8) * EMB + col] =
                    make_float2(s1.x + a[2] + b0, s1.y + a[3] + b1);
            }
        }
    }
}

// ---------------------------------------------------------------------------
// Kernel 3: tensor-core causal SiLU-attention, fused gating epilogue.
// Block = 128 q-rows x one (b,h). 8 warps, warp = 16 q-rows.
// qkv read from row-major split-bf16 (row (s*B+b), 128B at col h*64).
// 4-stage K pipeline (one __syncthreads per tile), 2 CTAs/SM target.
// ---------------------------------------------------------------------------
#define ATT_SM_Q 0            // Qhi 16K @0 | Qlo 16K @16384
#define ATT_SM_K 32768        // 4 stages x (Khi 8K | Klo 8K)
#define ATT_KSTG 16384
#define ATT_SMEM (32768 + 4 * ATT_KSTG)   // 98304

__device__ __forceinline__ void att_load_k(uint32_t sdst, int k0, int b, int h, int tid) {
    #pragma unroll
    for (int t = 0; t < 2; t++) {
        int idx = tid + t * 256;            // 0..511 -> 64 rows x 8 segs
        int row = idx >> 3, seg = idx & 7;
        uint32_t soff = row * 128 + ((seg ^ (row & 7)) << 4);
        size_t g = ((size_t)(k0 + row) * BATCH + b) * EMB + h * HDIM + seg * 8;
        CP16(sdst + soff, g_k_hi + g);
        CP16(sdst + 8192 + soff, g_k_lo + g);
    }
}

__global__ __launch_bounds__(256, 2) void attn_kernel() {
    extern __shared__ char smem[];
    uint32_t sb = smem_u32(smem);
    int tid = threadIdx.x, warp = tid >> 5, lane = tid & 31;
    int kvb = blockIdx.x;                 // 0..31 = b*16 + h
    int qb = (gridDim.y - 1) - blockIdx.y; // long (diagonal) blocks launch first
    int b = kvb >> 4, h = kvb & 15;

    int L = 2 * qb + 1;       // last k-tile index (inclusive)

    // Prologue: Q (128 rows) + K0 -> group0; K1 -> group1; K2 -> group2
    #pragma unroll
    for (int t = 0; t < 4; t++) {
        int idx = tid + t * 256;            // 0..1023 -> 128 rows x 8 segs
        int row = idx >> 3, seg = idx & 7;
        uint32_t soff = row * 128 + ((seg ^ (row & 7)) << 4);
        size_t g = ((size_t)(qb * 128 + row) * BATCH + b) * EMB + h * HDIM + seg * 8;
        CP16(sb + ATT_SM_Q + soff, g_k_hi + g);
        CP16(sb + ATT_SM_Q + 16384 + soff, g_k_lo + g);
    }
    att_load_k(sb + ATT_SM_K, 0, b, h, tid);
    CP_COMMIT();
    if (1 <= L) att_load_k(sb + ATT_SM_K + ATT_KSTG, 64, b, h, tid);
    CP_COMMIT();
    if (2 <= L) att_load_k(sb + ATT_SM_K + 2 * ATT_KSTG, 128, b, h, tid);
    CP_COMMIT();

    float oacc[8][4];
    #pragma unroll
    for (int i = 0; i < 8; i++)
        #pragma unroll
        for (int c = 0; c < 4; c++) oacc[i][c] = 0.f;

    for (int kt = 0; kt <= L; kt++) {
        CP_WAIT(2);
        __syncthreads();   // all warps done with tile kt-1; stage kt's data visible
        if (kt + 3 <= L)
            att_load_k(sb + ATT_SM_K + (uint32_t)((kt + 3) & 3) * ATT_KSTG,
                       (kt + 3) * 64, b, h, tid);
        CP_COMMIT();

        uint32_t sK = sb + ATT_SM_K + (uint32_t)(kt & 3) * ATT_KSTG;
        bool active = (kt * 64 <= qb * 128 + warp * 16 + 15);
        if (active) {
            // ---- scores: S = Q @ K^T (3-pass split), Q frags reloaded ----
            float sacc[8][4];
            #pragma unroll
            for (int i = 0; i < 8; i++)
                #pragma unroll
                for (int c = 0; c < 4; c++) sacc[i][c] = 0.f;
            #pragma unroll
            for (int ks = 0; ks < 4; ks++) {
                int rq = warp * 16 + (lane & 15);
                uint32_t qoff = rq * 128 + (((ks * 2 + (lane >> 4)) ^ (rq & 7)) << 4);
                uint32_t qh[4], ql[4];
                ldsm4(qh, sb + ATT_SM_Q + qoff);
                ldsm4(ql, sb + ATT_SM_Q + 16384 + qoff);
                #pragma unroll
                for (int p = 0; p < 4; p++) {
                    int r = p * 16 + (lane & 15);
                    uint32_t off = r * 128 + (((ks * 2 + (lane >> 4)) ^ (r & 7)) << 4);
                    uint32_t kh[4], kl[4];
                    ldsm4(kh, sK + off);
                    ldsm4(kl, sK + 8192 + off);
                    mma16816(sacc[2 * p],     qh, kh[0], kh[2]);
                    mma16816(sacc[2 * p],     qh, kl[0], kl[2]);
                    mma16816(sacc[2 * p],     ql, kh[0], kh[2]);
                    mma16816(sacc[2 * p + 1], qh, kh[1], kh[3]);
                    mma16816(sacc[2 * p + 1], qh, kl[1], kl[3]);
                    mma16816(sacc[2 * p + 1], ql, kh[1], kh[3]);
                }
            }
            // ---- scale + silu + causal mask ----
            bool need_mask = (kt * 64 + 63 > qb * 128 + warp * 16);
            int qrow0 = qb * 128 + warp * 16 + (lane >> 2);
            #pragma unroll
            for (int nt = 0; nt < 8; nt++) {
                int kcol0 = kt * 64 + nt * 8 + 2 * (lane & 3);
                #pragma unroll
                for (int c = 0; c < 4; c++) {
                    float w = silu_f(sacc[nt][c] * 0.125f);
                    if (need_mask) {
                        int q = qrow0 + ((c >= 2) ? 8 : 0);
                        int k = kcol0 + (c & 1);
                        if (k > q) w = 0.f;
                    }
                    sacc[nt][c] = w;
                }
            }
            // ---- W -> A-frags (hi/lo) for PV ----
            uint32_t ahi[4][4], alo[4][4];
            #pragma unroll
            for (int ks = 0; ks < 4; ks++) {
                split2(sacc[2 * ks][0],     sacc[2 * ks][1],     ahi[ks][0], alo[ks][0]);
                split2(sacc[2 * ks][2],     sacc[2 * ks][3],     ahi[ks][1], alo[ks][1]);
                split2(sacc[2 * ks + 1][0], sacc[2 * ks + 1][1], ahi[ks][2], alo[ks][2]);
                split2(sacc[2 * ks + 1][2], sacc[2 * ks + 1][3], ahi[ks][3], alo[ks][3]);
            }
            // ---- O += W @ V (V == K tile, trans-ldmatrix; 3-pass split) ----
            #pragma unroll
            for (int ks = 0; ks < 4; ks++) {
                #pragma unroll
                for (int p = 0; p < 4; p++) {
                    int r = ks * 16 + (lane & 15);
                    uint32_t off = r * 128 + (((p * 2 + (lane >> 4)) ^ (r & 7)) << 4);
                    uint32_t vh[4], vl[4];
                    ldsm4t(vh, sK + off);
                    ldsm4t(vl, sK + 8192 + off);
                    mma16816(oacc[2 * p],     ahi[ks], vh[0], vh[1]);
                    mma16816(oacc[2 * p],     ahi[ks], vl[0], vl[1]);
                    mma16816(oacc[2 * p],     alo[ks], vh[0], vh[1]);
                    mma16816(oacc[2 * p + 1], ahi[ks], vh[2], vh[3]);
                    mma16816(oacc[2 * p + 1], ahi[ks], vl[2], vl[3]);
                    mma16816(oacc[2 * p + 1], alo[ks], vh[2], vh[3]);
                }
            }
        }
    }

    // ---- Epilogue: gated = O * u -> split-bf16 for out_proj A ----
    int srow0 = qb * 128 + warp * 16 + (lane >> 2);
    int dp = 2 * (lane & 3);
    #pragma unroll
    for (int nt = 0; nt < 8; nt++) {
        int d = nt * 8 + dp;
        #pragma unroll
        for (int half = 0; half < 2; half++) {
            int s = srow0 + half * 8;
            size_t ix = ((size_t)s * BATCH + b) * EMB + h * HDIM + d;
            float2 uv = *(const float2*)&g_u[ix];
            float f0 = oacc[nt][half * 2]     * uv.x;
            float f1 = oacc[nt][half * 2 + 1] * uv.y;
            uint32_t hi, lo;
            split2(f0, f1, hi, lo);
            *(uint32_t*)((char*)g_gt_hi + ix * 2) = hi;
            *(uint32_t*)((char*)g_gt_lo + ix * 2) = lo;
        }
    }
}

// ---------------------------------------------------------------------------
extern "C" void kernel_launch(void* const* d_in, const int* in_sizes, int n_in,
                              void* d_out, int out_size) {
    const float* src   = (const float*)d_in[0];
    // d_in[1] = src_mask (causal tril) — predicate computed directly
    const float* in_w  = (const float*)d_in[2];
    const float* in_b  = (const float*)d_in[3];
    const float* out_w = (const float*)d_in[4];
    const float* out_b = (const float*)d_in[5];
    const float* ln_g  = (const float*)d_in[6];
    const float* ln_b  = (const float*)d_in[7];
    float* out = (float*)d_out;

    cudaFuncSetAttribute(attn_kernel, cudaFuncAttributeMaxDynamicSharedMemorySize, ATT_SMEM);
    cudaFuncSetAttribute(gemm_mma_kernel<0>, cudaFuncAttributeMaxDynamicSharedMemorySize, GEMM_SMEM);
    cudaFuncSetAttribute(gemm_mma_kernel<1>, cudaFuncAttributeMaxDynamicSharedMemorySize, GEMM_SMEM);

    ln_kernel<<<ROWS, 256>>>(src, ln_g, ln_b);
    wconv_kernel<<<3072, 256>>>(in_w, out_w);
    gemm_mma_kernel<0><<<dim3(2 * EMB / 128, ROWS / 128), 256, GEMM_SMEM>>>(
        in_b, nullptr, nullptr);
    attn_kernel<<<dim3(BATCH * HEADS, SEQ / 128), 256, ATT_SMEM>>>();
    gemm_mma_kernel<1><<<dim3(EMB / 128, ROWS / 128), 256, GEMM_SMEM>>>(
        out_b, src, out);
}

// round 12
// speedup vs baseline: 2.3322x; 1.1867x over previous
#include <cuda_runtime.h>
#include <cuda_bf16.h>
#include <math.h>
#include <stdint.h>

// Problem constants
#define SEQ 2048
#define BATCH 2
#define EMB 1024
#define HEADS 16
#define HDIM 64
#define ROWS (SEQ * BATCH)   // 4096

// ---------------------------------------------------------------------------
// Scratch (__device__ globals: allocation-free rule)
// ---------------------------------------------------------------------------
__device__ __align__(16) __nv_bfloat16 g_xn_hi[(size_t)ROWS * EMB];
__device__ __align__(16) __nv_bfloat16 g_xn_lo[(size_t)ROWS * EMB];
__device__ __align__(16) __nv_bfloat16 g_inw_hi[(size_t)2 * EMB * EMB];
__device__ __align__(16) __nv_bfloat16 g_inw_lo[(size_t)2 * EMB * EMB];
__device__ __align__(16) __nv_bfloat16 g_ow_hi[(size_t)EMB * EMB];
__device__ __align__(16) __nv_bfloat16 g_ow_lo[(size_t)EMB * EMB];
__device__ __align__(16) __nv_bfloat16 g_gt_hi[(size_t)ROWS * EMB];
__device__ __align__(16) __nv_bfloat16 g_gt_lo[(size_t)ROWS * EMB];
// qkv split-bf16, row-major [s*B+b][E] (d-contiguous per head: col h*64+d)
__device__ __align__(16) __nv_bfloat16 g_k_hi[(size_t)ROWS * EMB];
__device__ __align__(16) __nv_bfloat16 g_k_lo[(size_t)ROWS * EMB];
__device__ float g_u[(size_t)ROWS * EMB];

// fast silu: MUFU.EX2 + fast divide (2-ulp class; error << split-bf16 residual)
__device__ __forceinline__ float silu_f(float x) {
    return __fdividef(x, 1.0f + __expf(-x));
}

__device__ __forceinline__ uint32_t smem_u32(const void* p) {
    uint32_t a;
    asm("{ .reg .u64 t; cvta.to.shared.u64 t, %1; cvt.u32.u64 %0, t; }" : "=r"(a) : "l"(p));
    return a;
}

// Portable async-copy / ldmatrix / mma (compute_103-safe, sm_80+ ISA)
#define CP16(dst_u32, src_gptr) \
    asm volatile("cp.async.cg.shared.global [%0], [%1], 16;" \
                 :: "r"(dst_u32), "l"(__cvta_generic_to_global(src_gptr)) : "memory")
#define CP_COMMIT() asm volatile("cp.async.commit_group;" ::: "memory")
#define CP_WAIT(N)  asm volatile("cp.async.wait_group %0;" :: "n"(N) : "memory")

__device__ __forceinline__ void ldsm4(uint32_t* r, uint32_t addr) {
    asm volatile("ldmatrix.sync.aligned.m8n8.x4.shared.b16 {%0,%1,%2,%3}, [%4];"
                 : "=r"(r[0]), "=r"(r[1]), "=r"(r[2]), "=r"(r[3]) : "r"(addr));
}
__device__ __forceinline__ void ldsm4t(uint32_t* r, uint32_t addr) {
    asm volatile("ldmatrix.sync.aligned.m8n8.x4.trans.shared.b16 {%0,%1,%2,%3}, [%4];"
                 : "=r"(r[0]), "=r"(r[1]), "=r"(r[2]), "=r"(r[3]) : "r"(addr));
}
__device__ __forceinline__ void mma16816(float* c, const uint32_t* a,
                                         uint32_t b0, uint32_t b1) {
    asm volatile(
        "mma.sync.aligned.m16n8k16.row.col.f32.bf16.bf16.f32 "
        "{%0,%1,%2,%3}, {%4,%5,%6,%7}, {%8,%9}, {%0,%1,%2,%3};"
        : "+f"(c[0]), "+f"(c[1]), "+f"(c[2]), "+f"(c[3])
        : "r"(a[0]), "r"(a[1]), "r"(a[2]), "r"(a[3]), "r"(b0), "r"(b1));
}

__device__ __forceinline__ void split_bf16(float v, __nv_bfloat16& hi, __nv_bfloat16& lo) {
    hi = __float2bfloat16(v);
    lo = __float2bfloat16(v - __bfloat162float(hi));
}
// split two floats -> packed hi pair + lo pair (bf16x2 as uint32)
__device__ __forceinline__ void split2(float f0, float f1, uint32_t& hi, uint32_t& lo) {
    __nv_bfloat16 h0 = __float2bfloat16(f0);
    __nv_bfloat16 h1 = __float2bfloat16(f1);
    __nv_bfloat16 l0 = __float2bfloat16(f0 - __bfloat162float(h0));
    __nv_bfloat16 l1 = __float2bfloat16(f1 - __bfloat162float(h1));
    __nv_bfloat162 H = __halves2bfloat162(h0, h1);
    __nv_bfloat162 L = __halves2bfloat162(l0, l1);
    hi = *reinterpret_cast<uint32_t*>(&H);
    lo = *reinterpret_cast<uint32_t*>(&L);
}

// ---------------------------------------------------------------------------
// Kernel 1: LayerNorm -> split-bf16 xnorm. One block (256 thr) per row.
// ---------------------------------------------------------------------------
__global__ void ln_kernel(const float* __restrict__ src,
                          const float* __restrict__ gamma,
                          const float* __restrict__ beta) {
    int row = blockIdx.x;
    int t = threadIdx.x;
    const float4* x4 = (const float4*)(src + (size_t)row * EMB);
    float4 v = x4[t];
    float s = v.x + v.y + v.z + v.w;
    float q = v.x * v.x + v.y * v.y + v.z * v.z + v.w * v.w;
    #pragma unroll
    for (int o = 16; o > 0; o >>= 1) {
        s += __shfl_xor_sync(0xFFFFFFFFu, s, o);
        q += __shfl_xor_sync(0xFFFFFFFFu, q, o);
    }
    __shared__ float ss[8], sq[8];
    int w = t >> 5, l = t & 31;
    if (l == 0) { ss[w] = s; sq[w] = q; }
    __syncthreads();
    float st = 0.f, qt = 0.f;
    #pragma unroll
    for (int i = 0; i < 8; i++) { st += ss[i]; qt += sq[i]; }
    float mu = st * (1.0f / EMB);
    float var = qt * (1.0f / EMB) - mu * mu;
    float inv = rsqrtf(var + 1e-5f);
    float4 gg = ((const float4*)gamma)[t];
    float4 bb = ((const float4*)beta)[t];
    float o[4];
    o[0] = (v.x - mu) * inv * gg.x + bb.x;
    o[1] = (v.y - mu) * inv * gg.y + bb.y;
    o[2] = (v.z - mu) * inv * gg.z + bb.z;
    o[3] = (v.w - mu) * inv * gg.w + bb.w;
    size_t base = (size_t)row * EMB + t * 4;
    #pragma unroll
    for (int e = 0; e < 4; e++) {
        __nv_bfloat16 hi, lo;
        split_bf16(o[e], hi, lo);
        g_xn_hi[base + e] = hi;
        g_xn_lo[base + e] = lo;
    }
}

// ---------------------------------------------------------------------------
// Kernel 2: convert in_proj_w + out_proj_w fp32 -> split bf16
// ---------------------------------------------------------------------------
__global__ void wconv_kernel(const float* __restrict__ inw,
                             const float* __restrict__ outw) {
    const size_t N1 = (size_t)2 * EMB * EMB / 4;
    const size_t N2 = (size_t)EMB * EMB / 4;
    size_t i = (size_t)blockIdx.x * blockDim.x + threadIdx.x;
    if (i < N1) {
        float4 v = ((const float4*)inw)[i];
        float f[4] = {v.x, v.y, v.z, v.w};
        #pragma unroll
        for (int e = 0; e < 4; e++) {
            __nv_bfloat16 hi, lo;
            split_bf16(f[e], hi, lo);
            g_inw_hi[i * 4 + e] = hi;
            g_inw_lo[i * 4 + e] = lo;
        }
    } else if (i < N1 + N2) {
        size_t j = i - N1;
        float4 v = ((const float4*)outw)[j];
        float f[4] = {v.x, v.y, v.z, v.w};
        #pragma unroll
        for (int e = 0; e < 4; e++) {
            __nv_bfloat16 hi, lo;
            split_bf16(f[e], hi, lo);
            g_ow_hi[j * 4 + e] = hi;
            g_ow_lo[j * 4 + e] = lo;
        }
    }
}

// ---------------------------------------------------------------------------
// Split-bf16 GEMM via mma.sync:  C[M,N] = A[M,K] @ B[N,K]^T   (3-pass split)
// Block 128x128, BK=32, 8 warps (warp tile 32x64), 3-stage cp.async pipeline,
// 2 CTAs/SM (96 KB smem each).
// MODE 0 = in_proj (bias+silu -> qkv split-bf16 row-major / u fp32)
// MODE 1 = out_proj (src+bias -> out)
// ---------------------------------------------------------------------------
#define BK 32
#define NKS (EMB / BK)          // 32
#define STG_BYTES 32768
#define SUB_A_HI 0
#define SUB_A_LO 8192
#define SUB_B_HI 16384
#define SUB_B_LO 24576
#define GEMM_SMEM (3 * STG_BYTES)   // 98304

__device__ __forceinline__ void stage_load(uint32_t sdst,
                                           const __nv_bfloat16* __restrict__ Ahi,
                                           const __nv_bfloat16* __restrict__ Alo,
                                           const __nv_bfloat16* __restrict__ Bhi,
                                           const __nv_bfloat16* __restrict__ Blo,
                                           int bm, int bn, int k0, int tid) {
    #pragma unroll
    for (int t = 0; t < 2; t++) {
        int idx = tid + t * 256;            // 0..511
        int row = idx >> 2, seg = idx & 3;  // 128 rows x 4 x 16B
        uint32_t soff = row * 64 + ((seg ^ ((row >> 1) & 3)) << 4);
        size_t ga = (size_t)(bm + row) * EMB + k0 + seg * 8;
        size_t gb = (size_t)(bn + row) * EMB + k0 + seg * 8;
        CP16(sdst + SUB_A_HI + soff, Ahi + ga);
        CP16(sdst + SUB_A_LO + soff, Alo + ga);
        CP16(sdst + SUB_B_HI + soff, Bhi + gb);
        CP16(sdst + SUB_B_LO + soff, Blo + gb);
    }
}

template <int MODE>
__global__ __launch_bounds__(256, 2)
void gemm_mma_kernel(const float* __restrict__ bias,
                     const float* __restrict__ src,
                     float* __restrict__ out) {
    extern __shared__ char smem[];
    uint32_t sb = smem_u32(smem);
    int tid = threadIdx.x, warp = tid >> 5, lane = tid & 31;
    int bn = blockIdx.x * 128, bm = blockIdx.y * 128;

    const __nv_bfloat16 *Ahi, *Alo, *Bhi, *Blo;
    if (MODE == 0) { Ahi = g_xn_hi; Alo = g_xn_lo; Bhi = g_inw_hi; Blo = g_inw_lo; }
    else           { Ahi = g_gt_hi; Alo = g_gt_lo; Bhi = g_ow_hi;  Blo = g_ow_lo; }

    // prologue: stages 0,1
    #pragma unroll
    for (int s = 0; s < 2; s++) {
        stage_load(sb + s * STG_BYTES, Ahi, Alo, Bhi, Blo, bm, bn, s * BK, tid);
        CP_COMMIT();
    }

    int wm = (warp >> 1) * 32;
    int wn = (warp & 1) * 64;
    int lrow = lane & 15;
    int lseg = lane >> 4;

    float acc[2][8][4];
    #pragma unroll
    for (int a = 0; a < 2; a++)
        #pragma unroll
        for (int b = 0; b < 8; b++)
            #pragma unroll
            for (int c = 0; c < 4; c++) acc[a][b][c] = 0.f;

    int buf = 0;
    for (int kt = 0; kt < NKS; kt++) {
        CP_WAIT(1);
        __syncthreads();
        uint32_t st = sb + (uint32_t)buf * STG_BYTES;
        if (kt + 2 < NKS) {
            int nbuf = buf + 2; if (nbuf >= 3) nbuf -= 3;
            stage_load(sb + (uint32_t)nbuf * STG_BYTES, Ahi, Alo, Bhi, Blo,
                       bm, bn, (kt + 2) * BK, tid);
            CP_COMMIT();
        }
        if (++buf == 3) buf = 0;
        #pragma unroll
        for (int kk = 0; kk < 2; kk++) {
            int seg = kk * 2 + lseg;
            uint32_t ahi[2][4], alo[2][4];
            #pragma unroll
            for (int mt = 0; mt < 2; mt++) {
                int r = wm + mt * 16 + lrow;
                uint32_t off = r * 64 + ((seg ^ ((r >> 1) & 3)) << 4);
                ldsm4(ahi[mt], st + SUB_A_HI + off);
                ldsm4(alo[mt], st + SUB_A_LO + off);
            }
            #pragma unroll
            for (int p = 0; p < 4; p++) {
                int r = wn + p * 16 + lrow;
                uint32_t off = r * 64 + ((seg ^ ((r >> 1) & 3)) << 4);
                uint32_t bhi[4], blo[4];
                ldsm4(bhi, st + SUB_B_HI + off);
                ldsm4(blo, st + SUB_B_LO + off);
                #pragma unroll
                for (int mt = 0; mt < 2; mt++) {
                    mma16816(acc[mt][2 * p],     ahi[mt], bhi[0], bhi[2]);
                    mma16816(acc[mt][2 * p],     ahi[mt], blo[0], blo[2]);
                    mma16816(acc[mt][2 * p],     alo[mt], bhi[0], bhi[2]);
                    mma16816(acc[mt][2 * p + 1], ahi[mt], bhi[1], bhi[3]);
                    mma16816(acc[mt][2 * p + 1], ahi[mt], blo[1], blo[3]);
                    mma16816(acc[mt][2 * p + 1], alo[mt], bhi[1], bhi[3]);
                }
            }
        }
    }

    int r0 = bm + wm + (lane >> 2);
    int c0 = bn + wn + 2 * (lane & 3);
    #pragma unroll
    for (int mt = 0; mt < 2; mt++) {
        #pragma unroll
        for (int nt = 0; nt < 8; nt++) {
            int col = c0 + nt * 8;
            float* a = acc[mt][nt];
            int r = r0 + mt * 16;
            if (MODE == 0) {
                float b0 = bias[col], b1 = bias[col + 1];
                float v0 = silu_f(a[0] + b0);
                float v1 = silu_f(a[1] + b1);
                float v2 = silu_f(a[2] + b0);
                float v3 = silu_f(a[3] + b1);
                if (bn < EMB) {
                    // qkv half -> split-bf16, row-major (coalesced pair stores)
                    uint32_t hi, lo;
                    split2(v0, v1, hi, lo);
                    *(uint32_t*)((char*)g_k_hi + ((size_t)r * EMB + col) * 2) = hi;
                    *(uint32_t*)((char*)g_k_lo + ((size_t)r * EMB + col) * 2) = lo;
                    split2(v2, v3, hi, lo);
                    *(uint32_t*)((char*)g_k_hi + ((size_t)(r + 8) * EMB + col) * 2) = hi;
                    *(uint32_t*)((char*)g_k_lo + ((size_t)(r + 8) * EMB + col) * 2) = lo;
                } else {
                    int cc = col - EMB;
                    *(float2*)&g_u[(size_t)r * EMB + cc]       = make_float2(v0, v1);
                    *(float2*)&g_u[(size_t)(r + 8) * EMB + cc] = make_float2(v2, v3);
                }
            } else {
                float b0 = bias[col], b1 = bias[col + 1];
                float2 s0 = *(const float2*)&src[(size_t)r * EMB + col];
                float2 s1 = *(const float2*)&src[(size_t)(r + 8) * EMB + col];
                *(float2*)&out[(size_t)r * EMB + col] =
                    make_float2(s0.x + a[0] + b0, s0.y + a[1] + b1);
                *(float2*)&out[(size_t)(r + 8) * EMB + col] =
                    make_float2(s1.x + a[2] + b0, s1.y + a[3] + b1);
            }
        }
    }
}

// ---------------------------------------------------------------------------
// Kernel 3: tensor-core causal SiLU-attention, fused gating epilogue.
// Block = 128 q-rows x one (b,h). 8 warps, warp = 16 q-rows.
// qkv read from row-major split-bf16 (row (s*B+b), 128B at col h*64).
// 4-stage K pipeline (one __syncthreads per tile), 2 CTAs/SM.
// ---------------------------------------------------------------------------
#define ATT_SM_Q 0            // Qhi 16K @0 | Qlo 16K @16384
#define ATT_SM_K 32768        // 4 stages x (Khi 8K | Klo 8K)
#define ATT_KSTG 16384
#define ATT_SMEM (32768 + 4 * ATT_KSTG)   // 98304

__device__ __forceinline__ void att_load_k(uint32_t sdst, int k0, int b, int h, int tid) {
    #pragma unroll
    for (int t = 0; t < 2; t++) {
        int idx = tid + t * 256;            // 0..511 -> 64 rows x 8 segs
        int row = idx >> 3, seg = idx & 7;
        uint32_t soff = row * 128 + ((seg ^ (row & 7)) << 4);
        size_t g = ((size_t)(k0 + row) * BATCH + b) * EMB + h * HDIM + seg * 8;
        CP16(sdst + soff, g_k_hi + g);
        CP16(sdst + 8192 + soff, g_k_lo + g);
    }
}

__global__ __launch_bounds__(256, 2) void attn_kernel() {
    extern __shared__ char smem[];
    uint32_t sb = smem_u32(smem);
    int tid = threadIdx.x, warp = tid >> 5, lane = tid & 31;
    int kvb = blockIdx.x;                 // 0..31 = b*16 + h
    int qb = (gridDim.y - 1) - blockIdx.y; // long (diagonal) blocks launch first
    int b = kvb >> 4, h = kvb & 15;

    int L = 2 * qb + 1;       // last k-tile index (inclusive)

    // Prologue: Q (128 rows) + K0 -> group0; K1 -> group1; K2 -> group2
    #pragma unroll
    for (int t = 0; t < 4; t++) {
        int idx = tid + t * 256;            // 0..1023 -> 128 rows x 8 segs
        int row = idx >> 3, seg = idx & 7;
        uint32_t soff = row * 128 + ((seg ^ (row & 7)) << 4);
        size_t g = ((size_t)(qb * 128 + row) * BATCH + b) * EMB + h * HDIM + seg * 8;
        CP16(sb + ATT_SM_Q + soff, g_k_hi + g);
        CP16(sb + ATT_SM_Q + 16384 + soff, g_k_lo + g);
    }
    att_load_k(sb + ATT_SM_K, 0, b, h, tid);
    CP_COMMIT();
    if (1 <= L) att_load_k(sb + ATT_SM_K + ATT_KSTG, 64, b, h, tid);
    CP_COMMIT();
    if (2 <= L) att_load_k(sb + ATT_SM_K + 2 * ATT_KSTG, 128, b, h, tid);
    CP_COMMIT();

    float oacc[8][4];
    #pragma unroll
    for (int i = 0; i < 8; i++)
        #pragma unroll
        for (int c = 0; c < 4; c++) oacc[i][c] = 0.f;

    for (int kt = 0; kt <= L; kt++) {
        CP_WAIT(2);
        __syncthreads();   // all warps done with tile kt-1; stage kt's data visible
        if (kt + 3 <= L)
            att_load_k(sb + ATT_SM_K + (uint32_t)((kt + 3) & 3) * ATT_KSTG,
                       (kt + 3) * 64, b, h, tid);
        CP_COMMIT();

        uint32_t sK = sb + ATT_SM_K + (uint32_t)(kt & 3) * ATT_KSTG;
        bool active = (kt * 64 <= qb * 128 + warp * 16 + 15);
        if (active) {
            // ---- scores: S = Q @ K^T (3-pass split), Q frags reloaded ----
            float sacc[8][4];
            #pragma unroll
            for (int i = 0; i < 8; i++)
                #pragma unroll
                for (int c = 0; c < 4; c++) sacc[i][c] = 0.f;
            #pragma unroll
            for (int ks = 0; ks < 4; ks++) {
                int rq = warp * 16 + (lane & 15);
                uint32_t qoff = rq * 128 + (((ks * 2 + (lane >> 4)) ^ (rq & 7)) << 4);
                uint32_t qh[4], ql[4];
                ldsm4(qh, sb + ATT_SM_Q + qoff);
                ldsm4(ql, sb + ATT_SM_Q + 16384 + qoff);
                #pragma unroll
                for (int p = 0; p < 4; p++) {
                    int r = p * 16 + (lane & 15);
                    uint32_t off = r * 128 + (((ks * 2 + (lane >> 4)) ^ (r & 7)) << 4);
                    uint32_t kh[4], kl[4];
                    ldsm4(kh, sK + off);
                    ldsm4(kl, sK + 8192 + off);
                    mma16816(sacc[2 * p],     qh, kh[0], kh[2]);
                    mma16816(sacc[2 * p],     qh, kl[0], kl[2]);
                    mma16816(sacc[2 * p],     ql, kh[0], kh[2]);
                    mma16816(sacc[2 * p + 1], qh, kh[1], kh[3]);
                    mma16816(sacc[2 * p + 1], qh, kl[1], kl[3]);
                    mma16816(sacc[2 * p + 1], ql, kh[1], kh[3]);
                }
            }
            // ---- scale + silu + causal mask ----
            bool need_mask = (kt * 64 + 63 > qb * 128 + warp * 16);
            int qrow0 = qb * 128 + warp * 16 + (lane >> 2);
            #pragma unroll
            for (int nt = 0; nt < 8; nt++) {
                int kcol0 = kt * 64 + nt * 8 + 2 * (lane & 3);
                #pragma unroll
                for (int c = 0; c < 4; c++) {
                    float w = silu_f(sacc[nt][c] * 0.125f);
                    if (need_mask) {
                        int q = qrow0 + ((c >= 2) ? 8 : 0);
                        int k = kcol0 + (c & 1);
                        if (k > q) w = 0.f;
                    }
                    sacc[nt][c] = w;
                }
            }
            // ---- W -> A-frags (hi/lo) for PV ----
            uint32_t ahi[4][4], alo[4][4];
            #pragma unroll
            for (int ks = 0; ks < 4; ks++) {
                split2(sacc[2 * ks][0],     sacc[2 * ks][1],     ahi[ks][0], alo[ks][0]);
                split2(sacc[2 * ks][2],     sacc[2 * ks][3],     ahi[ks][1], alo[ks][1]);
                split2(sacc[2 * ks + 1][0], sacc[2 * ks + 1][1], ahi[ks][2], alo[ks][2]);
                split2(sacc[2 * ks + 1][2], sacc[2 * ks + 1][3], ahi[ks][3], alo[ks][3]);
            }
            // ---- O += W @ V (V == K tile, trans-ldmatrix; 3-pass split) ----
            #pragma unroll
            for (int ks = 0; ks < 4; ks++) {
                #pragma unroll
                for (int p = 0; p < 4; p++) {
                    int r = ks * 16 + (lane & 15);
                    uint32_t off = r * 128 + (((p * 2 + (lane >> 4)) ^ (r & 7)) << 4);
                    uint32_t vh[4], vl[4];
                    ldsm4t(vh, sK + off);
                    ldsm4t(vl, sK + 8192 + off);
                    mma16816(oacc[2 * p],     ahi[ks], vh[0], vh[1]);
                    mma16816(oacc[2 * p],     ahi[ks], vl[0], vl[1]);
                    mma16816(oacc[2 * p],     alo[ks], vh[0], vh[1]);
                    mma16816(oacc[2 * p + 1], ahi[ks], vh[2], vh[3]);
                    mma16816(oacc[2 * p + 1], ahi[ks], vl[2], vl[3]);
                    mma16816(oacc[2 * p + 1], alo[ks], vh[2], vh[3]);
                }
            }
        }
    }

    // ---- Epilogue: gated = O * u -> split-bf16 for out_proj A ----
    int srow0 = qb * 128 + warp * 16 + (lane >> 2);
    int dp = 2 * (lane & 3);
    #pragma unroll
    for (int nt = 0; nt < 8; nt++) {
        int d = nt * 8 + dp;
        #pragma unroll
        for (int half = 0; half < 2; half++) {
            int s = srow0 + half * 8;
            size_t ix = ((size_t)s * BATCH + b) * EMB + h * HDIM + d;
            float2 uv = *(const float2*)&g_u[ix];
            float f0 = oacc[nt][half * 2]     * uv.x;
            float f1 = oacc[nt][half * 2 + 1] * uv.y;
            uint32_t hi, lo;
            split2(f0, f1, hi, lo);
            *(uint32_t*)((char*)g_gt_hi + ix * 2) = hi;
            *(uint32_t*)((char*)g_gt_lo + ix * 2) = lo;
        }
    }
}

// ---------------------------------------------------------------------------
extern "C" void kernel_launch(void* const* d_in, const int* in_sizes, int n_in,
                              void* d_out, int out_size) {
    const float* src   = (const float*)d_in[0];
    // d_in[1] = src_mask (causal tril) — predicate computed directly
    const float* in_w  = (const float*)d_in[2];
    const float* in_b  = (const float*)d_in[3];
    const float* out_w = (const float*)d_in[4];
    const float* out_b = (const float*)d_in[5];
    const float* ln_g  = (const float*)d_in[6];
    const float* ln_b  = (const float*)d_in[7];
    float* out = (float*)d_out;

    cudaFuncSetAttribute(attn_kernel, cudaFuncAttributeMaxDynamicSharedMemorySize, ATT_SMEM);
    cudaFuncSetAttribute(gemm_mma_kernel<0>, cudaFuncAttributeMaxDynamicSharedMemorySize, GEMM_SMEM);
    cudaFuncSetAttribute(gemm_mma_kernel<1>, cudaFuncAttributeMaxDynamicSharedMemorySize, GEMM_SMEM);

    ln_kernel<<<ROWS, 256>>>(src, ln_g, ln_b);
    wconv_kernel<<<3072, 256>>>(in_w, out_w);
    gemm_mma_kernel<0><<<dim3(2 * EMB / 128, ROWS / 128), 256, GEMM_SMEM>>>(
        in_b, nullptr, nullptr);
    attn_kernel<<<dim3(BATCH * HEADS, SEQ / 128), 256, ATT_SMEM>>>();
    gemm_mma_kernel<1><<<dim3(EMB / 128, ROWS / 128), 256, GEMM_SMEM>>>(
        out_b, src, out);
}

// round 13
// speedup vs baseline: 2.9044x; 1.2453x over previous
#include <cuda_runtime.h>
#include <cuda_fp16.h>
#include <math.h>
#include <stdint.h>

// Problem constants
#define SEQ 2048
#define BATCH 2
#define EMB 1024
#define HEADS 16
#define HDIM 64
#define ROWS (SEQ * BATCH)   // 4096

// ---------------------------------------------------------------------------
// Scratch (__device__ globals: allocation-free rule). All fp16 split now.
// Weights: HI ONLY (2-pass projections). Activations: hi+lo.
// ---------------------------------------------------------------------------
__device__ __align__(16) __half g_xn_hi[(size_t)ROWS * EMB];
__device__ __align__(16) __half g_xn_lo[(size_t)ROWS * EMB];
__device__ __align__(16) __half g_inw_h[(size_t)2 * EMB * EMB];
__device__ __align__(16) __half g_ow_h[(size_t)EMB * EMB];
__device__ __align__(16) __half g_gt_hi[(size_t)ROWS * EMB];
__device__ __align__(16) __half g_gt_lo[(size_t)ROWS * EMB];
// qkv split-fp16, row-major [s*B+b][E] (d-contiguous per head: col h*64+d)
__device__ __align__(16) __half g_k_hi[(size_t)ROWS * EMB];
__device__ __align__(16) __half g_k_lo[(size_t)ROWS * EMB];
__device__ float g_u[(size_t)ROWS * EMB];

// fast silu: MUFU.EX2 + fast divide (2-ulp class; error << split residual)
__device__ __forceinline__ float silu_f(float x) {
    return __fdividef(x, 1.0f + __expf(-x));
}

__device__ __forceinline__ uint32_t smem_u32(const void* p) {
    uint32_t a;
    asm("{ .reg .u64 t; cvta.to.shared.u64 t, %1; cvt.u32.u64 %0, t; }" : "=r"(a) : "l"(p));
    return a;
}

// Portable async-copy / ldmatrix / mma (compute_103-safe, sm_80+ ISA)
#define CP16(dst_u32, src_gptr) \
    asm volatile("cp.async.cg.shared.global [%0], [%1], 16;" \
                 :: "r"(dst_u32), "l"(__cvta_generic_to_global(src_gptr)) : "memory")
#define CP_COMMIT() asm volatile("cp.async.commit_group;" ::: "memory")
#define CP_WAIT(N)  asm volatile("cp.async.wait_group %0;" :: "n"(N) : "memory")

__device__ __forceinline__ void ldsm4(uint32_t* r, uint32_t addr) {
    asm volatile("ldmatrix.sync.aligned.m8n8.x4.shared.b16 {%0,%1,%2,%3}, [%4];"
                 : "=r"(r[0]), "=r"(r[1]), "=r"(r[2]), "=r"(r[3]) : "r"(addr));
}
__device__ __forceinline__ void ldsm4t(uint32_t* r, uint32_t addr) {
    asm volatile("ldmatrix.sync.aligned.m8n8.x4.trans.shared.b16 {%0,%1,%2,%3}, [%4];"
                 : "=r"(r[0]), "=r"(r[1]), "=r"(r[2]), "=r"(r[3]) : "r"(addr));
}
// fp16 mma, fp32 accumulate
__device__ __forceinline__ void mma16816(float* c, const uint32_t* a,
                                         uint32_t b0, uint32_t b1) {
    asm volatile(
        "mma.sync.aligned.m16n8k16.row.col.f32.f16.f16.f32 "
        "{%0,%1,%2,%3}, {%4,%5,%6,%7}, {%8,%9}, {%0,%1,%2,%3};"
        : "+f"(c[0]), "+f"(c[1]), "+f"(c[2]), "+f"(c[3])
        : "r"(a[0]), "r"(a[1]), "r"(a[2]), "r"(a[3]), "r"(b0), "r"(b1));
}

__device__ __forceinline__ void split_h(float v, __half& hi, __half& lo) {
    hi = __float2half(v);
    lo = __float2half(v - __half2float(hi));
}
// split two floats -> packed hi pair + lo pair (half2 as uint32)
__device__ __forceinline__ void split2(float f0, float f1, uint32_t& hi, uint32_t& lo) {
    __half h0 = __float2half(f0);
    __half h1 = __float2half(f1);
    __half l0 = __float2half(f0 - __half2float(h0));
    __half l1 = __float2half(f1 - __half2float(h1));
    __half2 H = __halves2half2(h0, h1);
    __half2 L = __halves2half2(l0, l1);
    hi = *reinterpret_cast<uint32_t*>(&H);
    lo = *reinterpret_cast<uint32_t*>(&L);
}

// ---------------------------------------------------------------------------
// Kernel 1: LayerNorm -> split-fp16 xnorm. One block (256 thr) per row.
// ---------------------------------------------------------------------------
__global__ void ln_kernel(const float* __restrict__ src,
                          const float* __restrict__ gamma,
                          const float* __restrict__ beta) {
    int row = blockIdx.x;
    int t = threadIdx.x;
    const float4* x4 = (const float4*)(src + (size_t)row * EMB);
    float4 v = x4[t];
    float s = v.x + v.y + v.z + v.w;
    float q = v.x * v.x + v.y * v.y + v.z * v.z + v.w * v.w;
    #pragma unroll
    for (int o = 16; o > 0; o >>= 1) {
        s += __shfl_xor_sync(0xFFFFFFFFu, s, o);
        q += __shfl_xor_sync(0xFFFFFFFFu, q, o);
    }
    __shared__ float ss[8], sq[8];
    int w = t >> 5, l = t & 31;
    if (l == 0) { ss[w] = s; sq[w] = q; }
    __syncthreads();
    float st = 0.f, qt = 0.f;
    #pragma unroll
    for (int i = 0; i < 8; i++) { st += ss[i]; qt += sq[i]; }
    float mu = st * (1.0f / EMB);
    float var = qt * (1.0f / EMB) - mu * mu;
    float inv = rsqrtf(var + 1e-5f);
    float4 gg = ((const float4*)gamma)[t];
    float4 bb = ((const float4*)beta)[t];
    float o[4];
    o[0] = (v.x - mu) * inv * gg.x + bb.x;
    o[1] = (v.y - mu) * inv * gg.y + bb.y;
    o[2] = (v.z - mu) * inv * gg.z + bb.z;
    o[3] = (v.w - mu) * inv * gg.w + bb.w;
    size_t base = (size_t)row * EMB + t * 4;
    #pragma unroll
    for (int e = 0; e < 4; e++) {
        __half hi, lo;
        split_h(o[e], hi, lo);
        g_xn_hi[base + e] = hi;
        g_xn_lo[base + e] = lo;
    }
}

// ---------------------------------------------------------------------------
// Kernel 2: convert in_proj_w + out_proj_w fp32 -> fp16 (hi only; 2-pass GEMM)
// ---------------------------------------------------------------------------
__global__ void wconv_kernel(const float* __restrict__ inw,
                             const float* __restrict__ outw) {
    const size_t N1 = (size_t)2 * EMB * EMB / 4;
    const size_t N2 = (size_t)EMB * EMB / 4;
    size_t i = (size_t)blockIdx.x * blockDim.x + threadIdx.x;
    if (i < N1) {
        float4 v = ((const float4*)inw)[i];
        __half2 p0 = __halves2half2(__float2half(v.x), __float2half(v.y));
        __half2 p1 = __halves2half2(__float2half(v.z), __float2half(v.w));
        *(__half2*)&g_inw_h[i * 4]     = p0;
        *(__half2*)&g_inw_h[i * 4 + 2] = p1;
    } else if (i < N1 + N2) {
        size_t j = i - N1;
        float4 v = ((const float4*)outw)[j];
        __half2 p0 = __halves2half2(__float2half(v.x), __float2half(v.y));
        __half2 p1 = __halves2half2(__float2half(v.z), __float2half(v.w));
        *(__half2*)&g_ow_h[j * 4]     = p0;
        *(__half2*)&g_ow_h[j * 4 + 2] = p1;
    }
}

// ---------------------------------------------------------------------------
// Split-fp16 2-pass GEMM via mma.sync:  C = (Ahi+Alo) @ Bhi^T
// Block 128x128, BK=32, 8 warps (warp tile 32x64), 3-stage cp.async pipeline.
// Stage = Ahi | Alo | Bhi (24 KB). 2 CTAs/SM.
// MODE 0 = in_proj (bias+silu -> qkv split-fp16 row-major / u fp32)
// MODE 1 = out_proj (src+bias -> out)
// ---------------------------------------------------------------------------
#define BK 32
#define NKS (EMB / BK)          // 32
#define STG_BYTES 24576
#define SUB_A_HI 0
#define SUB_A_LO 8192
#define SUB_B_HI 16384
#define GEMM_SMEM (3 * STG_BYTES)   // 73728

__device__ __forceinline__ void stage_load(uint32_t sdst,
                                           const __half* __restrict__ Ahi,
                                           const __half* __restrict__ Alo,
                                           const __half* __restrict__ Bhi,
                                           int bm, int bn, int k0, int tid) {
    #pragma unroll
    for (int t = 0; t < 2; t++) {
        int idx = tid + t * 256;            // 0..511
        int row = idx >> 2, seg = idx & 3;  // 128 rows x 4 x 16B
        uint32_t soff = row * 64 + ((seg ^ ((row >> 1) & 3)) << 4);
        size_t ga = (size_t)(bm + row) * EMB + k0 + seg * 8;
        size_t gb = (size_t)(bn + row) * EMB + k0 + seg * 8;
        CP16(sdst + SUB_A_HI + soff, Ahi + ga);
        CP16(sdst + SUB_A_LO + soff, Alo + ga);
        CP16(sdst + SUB_B_HI + soff, Bhi + gb);
    }
}

template <int MODE>
__global__ __launch_bounds__(256, 2)
void gemm_mma_kernel(const float* __restrict__ bias,
                     const float* __restrict__ src,
                     float* __restrict__ out) {
    extern __shared__ char smem[];
    uint32_t sb = smem_u32(smem);
    int tid = threadIdx.x, warp = tid >> 5, lane = tid & 31;
    int bn = blockIdx.x * 128, bm = blockIdx.y * 128;

    const __half *Ahi, *Alo, *Bhi;
    if (MODE == 0) { Ahi = g_xn_hi; Alo = g_xn_lo; Bhi = g_inw_h; }
    else           { Ahi = g_gt_hi; Alo = g_gt_lo; Bhi = g_ow_h; }

    // prologue: stages 0,1
    #pragma unroll
    for (int s = 0; s < 2; s++) {
        stage_load(sb + s * STG_BYTES, Ahi, Alo, Bhi, bm, bn, s * BK, tid);
        CP_COMMIT();
    }

    int wm = (warp >> 1) * 32;
    int wn = (warp & 1) * 64;
    int lrow = lane & 15;
    int lseg = lane >> 4;

    float acc[2][8][4];
    #pragma unroll
    for (int a = 0; a < 2; a++)
        #pragma unroll
        for (int b = 0; b < 8; b++)
            #pragma unroll
            for (int c = 0; c < 4; c++) acc[a][b][c] = 0.f;

    int buf = 0;
    for (int kt = 0; kt < NKS; kt++) {
        CP_WAIT(1);
        __syncthreads();
        uint32_t st = sb + (uint32_t)buf * STG_BYTES;
        if (kt + 2 < NKS) {
            int nbuf = buf + 2; if (nbuf >= 3) nbuf -= 3;
            stage_load(sb + (uint32_t)nbuf * STG_BYTES, Ahi, Alo, Bhi,
                       bm, bn, (kt + 2) * BK, tid);
            CP_COMMIT();
        }
        if (++buf == 3) buf = 0;
        #pragma unroll
        for (int kk = 0; kk < 2; kk++) {
            int seg = kk * 2 + lseg;
            uint32_t ahi[2][4], alo[2][4];
            #pragma unroll
            for (int mt = 0; mt < 2; mt++) {
                int r = wm + mt * 16 + lrow;
                uint32_t off = r * 64 + ((seg ^ ((r >> 1) & 3)) << 4);
                ldsm4(ahi[mt], st + SUB_A_HI + off);
                ldsm4(alo[mt], st + SUB_A_LO + off);
            }
            #pragma unroll
            for (int p = 0; p < 4; p++) {
                int r = wn + p * 16 + lrow;
                uint32_t off = r * 64 + ((seg ^ ((r >> 1) & 3)) << 4);
                uint32_t bhi[4];
                ldsm4(bhi, st + SUB_B_HI + off);
                #pragma unroll
                for (int mt = 0; mt < 2; mt++) {
                    mma16816(acc[mt][2 * p],     ahi[mt], bhi[0], bhi[2]);
                    mma16816(acc[mt][2 * p],     alo[mt], bhi[0], bhi[2]);
                    mma16816(acc[mt][2 * p + 1], ahi[mt], bhi[1], bhi[3]);
                    mma16816(acc[mt][2 * p + 1], alo[mt], bhi[1], bhi[3]);
                }
            }
        }
    }

    int r0 = bm + wm + (lane >> 2);
    int c0 = bn + wn + 2 * (lane & 3);
    #pragma unroll
    for (int mt = 0; mt < 2; mt++) {
        #pragma unroll
        for (int nt = 0; nt < 8; nt++) {
            int col = c0 + nt * 8;
            float* a = acc[mt][nt];
            int r = r0 + mt * 16;
            if (MODE == 0) {
                float b0 = bias[col], b1 = bias[col + 1];
                float v0 = silu_f(a[0] + b0);
                float v1 = silu_f(a[1] + b1);
                float v2 = silu_f(a[2] + b0);
                float v3 = silu_f(a[3] + b1);
                if (bn < EMB) {
                    // qkv half -> split-fp16, row-major (coalesced pair stores)
                    uint32_t hi, lo;
                    split2(v0, v1, hi, lo);
                    *(uint32_t*)((char*)g_k_hi + ((size_t)r * EMB + col) * 2) = hi;
                    *(uint32_t*)((char*)g_k_lo + ((size_t)r * EMB + col) * 2) = lo;
                    split2(v2, v3, hi, lo);
                    *(uint32_t*)((char*)g_k_hi + ((size_t)(r + 8) * EMB + col) * 2) = hi;
                    *(uint32_t*)((char*)g_k_lo + ((size_t)(r + 8) * EMB + col) * 2) = lo;
                } else {
                    int cc = col - EMB;
                    *(float2*)&g_u[(size_t)r * EMB + cc]       = make_float2(v0, v1);
                    *(float2*)&g_u[(size_t)(r + 8) * EMB + cc] = make_float2(v2, v3);
                }
            } else {
                float b0 = bias[col], b1 = bias[col + 1];
                float2 s0 = *(const float2*)&src[(size_t)r * EMB + col];
                float2 s1 = *(const float2*)&src[(size_t)(r + 8) * EMB + col];
                *(float2*)&out[(size_t)r * EMB + col] =
                    make_float2(s0.x + a[0] + b0, s0.y + a[1] + b1);
                *(float2*)&out[(size_t)(r + 8) * EMB + col] =
                    make_float2(s1.x + a[2] + b0, s1.y + a[3] + b1);
            }
        }
    }
}

// ---------------------------------------------------------------------------
// Kernel 3: tensor-core causal SiLU-attention (fp16 3-pass), fused gating.
// Block = 128 q-rows x one (b,h). 8 warps, warp = 16 q-rows.
// 4-stage K pipeline (one __syncthreads per tile), 2 CTAs/SM.
// ---------------------------------------------------------------------------
#define ATT_SM_Q 0            // Qhi 16K @0 | Qlo 16K @16384
#define ATT_SM_K 32768        // 4 stages x (Khi 8K | Klo 8K)
#define ATT_KSTG 16384
#define ATT_SMEM (32768 + 4 * ATT_KSTG)   // 98304

__device__ __forceinline__ void att_load_k(uint32_t sdst, int k0, int b, int h, int tid) {
    #pragma unroll
    for (int t = 0; t < 2; t++) {
        int idx = tid + t * 256;            // 0..511 -> 64 rows x 8 segs
        int row = idx >> 3, seg = idx & 7;
        uint32_t soff = row * 128 + ((seg ^ (row & 7)) << 4);
        size_t g = ((size_t)(k0 + row) * BATCH + b) * EMB + h * HDIM + seg * 8;
        CP16(sdst + soff, g_k_hi + g);
        CP16(sdst + 8192 + soff, g_k_lo + g);
    }
}

__global__ __launch_bounds__(256, 2) void attn_kernel() {
    extern __shared__ char smem[];
    uint32_t sb = smem_u32(smem);
    int tid = threadIdx.x, warp = tid >> 5, lane = tid & 31;
    int kvb = blockIdx.x;                 // 0..31 = b*16 + h
    int qb = (gridDim.y - 1) - blockIdx.y; // long (diagonal) blocks launch first
    int b = kvb >> 4, h = kvb & 15;

    int L = 2 * qb + 1;       // last k-tile index (inclusive)

    // Prologue: Q (128 rows) + K0 -> group0; K1 -> group1; K2 -> group2
    #pragma unroll
    for (int t = 0; t < 4; t++) {
        int idx = tid + t * 256;            // 0..1023 -> 128 rows x 8 segs
        int row = idx >> 3, seg = idx & 7;
        uint32_t soff = row * 128 + ((seg ^ (row & 7)) << 4);
        size_t g = ((size_t)(qb * 128 + row) * BATCH + b) * EMB + h * HDIM + seg * 8;
        CP16(sb + ATT_SM_Q + soff, g_k_hi + g);
        CP16(sb + ATT_SM_Q + 16384 + soff, g_k_lo + g);
    }
    att_load_k(sb + ATT_SM_K, 0, b, h, tid);
    CP_COMMIT();
    if (1 <= L) att_load_k(sb + ATT_SM_K + ATT_KSTG, 64, b, h, tid);
    CP_COMMIT();
    if (2 <= L) att_load_k(sb + ATT_SM_K + 2 * ATT_KSTG, 128, b, h, tid);
    CP_COMMIT();

    float oacc[8][4];
    #pragma unroll
    for (int i = 0; i < 8; i++)
        #pragma unroll
        for (int c = 0; c < 4; c++) oacc[i][c] = 0.f;

    for (int kt = 0; kt <= L; kt++) {
        CP_WAIT(2);
        __syncthreads();   // all warps done with tile kt-1; stage kt's data visible
        if (kt + 3 <= L)
            att_load_k(sb + ATT_SM_K + (uint32_t)((kt + 3) & 3) * ATT_KSTG,
                       (kt + 3) * 64, b, h, tid);
        CP_COMMIT();

        uint32_t sK = sb + ATT_SM_K + (uint32_t)(kt & 3) * ATT_KSTG;
        bool active = (kt * 64 <= qb * 128 + warp * 16 + 15);
        if (active) {
            // ---- scores: S = Q @ K^T (3-pass split), Q frags reloaded ----
            float sacc[8][4];
            #pragma unroll
            for (int i = 0; i < 8; i++)
                #pragma unroll
                for (int c = 0; c < 4; c++) sacc[i][c] = 0.f;
            #pragma unroll
            for (int ks = 0; ks < 4; ks++) {
                int rq = warp * 16 + (lane & 15);
                uint32_t qoff = rq * 128 + (((ks * 2 + (lane >> 4)) ^ (rq & 7)) << 4);
                uint32_t qh[4], ql[4];
                ldsm4(qh, sb + ATT_SM_Q + qoff);
                ldsm4(ql, sb + ATT_SM_Q + 16384 + qoff);
                #pragma unroll
                for (int p = 0; p < 4; p++) {
                    int r = p * 16 + (lane & 15);
                    uint32_t off = r * 128 + (((ks * 2 + (lane >> 4)) ^ (r & 7)) << 4);
                    uint32_t kh[4], kl[4];
                    ldsm4(kh, sK + off);
                    ldsm4(kl, sK + 8192 + off);
                    mma16816(sacc[2 * p],     qh, kh[0], kh[2]);
                    mma16816(sacc[2 * p],     qh, kl[0], kl[2]);
                    mma16816(sacc[2 * p],     ql, kh[0], kh[2]);
                    mma16816(sacc[2 * p + 1], qh, kh[1], kh[3]);
                    mma16816(sacc[2 * p + 1], qh, kl[1], kl[3]);
                    mma16816(sacc[2 * p + 1], ql, kh[1], kh[3]);
                }
            }
            // ---- scale + silu + causal mask ----
            bool need_mask = (kt * 64 + 63 > qb * 128 + warp * 16);
            int qrow0 = qb * 128 + warp * 16 + (lane >> 2);
            #pragma unroll
            for (int nt = 0; nt < 8; nt++) {
                int kcol0 = kt * 64 + nt * 8 + 2 * (lane & 3);
                #pragma unroll
                for (int c = 0; c < 4; c++) {
                    float w = silu_f(sacc[nt][c] * 0.125f);
                    if (need_mask) {
                        int q = qrow0 + ((c >= 2) ? 8 : 0);
                        int k = kcol0 + (c & 1);
                        if (k > q) w = 0.f;
                    }
                    sacc[nt][c] = w;
                }
            }
            // ---- W -> A-frags (hi/lo) for PV ----
            uint32_t ahi[4][4], alo[4][4];
            #pragma unroll
            for (int ks = 0; ks < 4; ks++) {
                split2(sacc[2 * ks][0],     sacc[2 * ks][1],     ahi[ks][0], alo[ks][0]);
                split2(sacc[2 * ks][2],     sacc[2 * ks][3],     ahi[ks][1], alo[ks][1]);
                split2(sacc[2 * ks + 1][0], sacc[2 * ks + 1][1], ahi[ks][2], alo[ks][2]);
                split2(sacc[2 * ks + 1][2], sacc[2 * ks + 1][3], ahi[ks][3], alo[ks][3]);
            }
            // ---- O += W @ V (V == K tile, trans-ldmatrix; 3-pass split) ----
            #pragma unroll
            for (int ks = 0; ks < 4; ks++) {
                #pragma unroll
                for (int p = 0; p < 4; p++) {
                    int r = ks * 16 + (lane & 15);
                    uint32_t off = r * 128 + (((p * 2 + (lane >> 4)) ^ (r & 7)) << 4);
                    uint32_t vh[4], vl[4];
                    ldsm4t(vh, sK + off);
                    ldsm4t(vl, sK + 8192 + off);
                    mma16816(oacc[2 * p],     ahi[ks], vh[0], vh[1]);
                    mma16816(oacc[2 * p],     ahi[ks], vl[0], vl[1]);
                    mma16816(oacc[2 * p],     alo[ks], vh[0], vh[1]);
                    mma16816(oacc[2 * p + 1], ahi[ks], vh[2], vh[3]);
                    mma16816(oacc[2 * p + 1], ahi[ks], vl[2], vl[3]);
                    mma16816(oacc[2 * p + 1], alo[ks], vh[2], vh[3]);
                }
            }
        }
    }

    // ---- Epilogue: gated = O * u -> split-fp16 for out_proj A ----
    int srow0 = qb * 128 + warp * 16 + (lane >> 2);
    int dp = 2 * (lane & 3);
    #pragma unroll
    for (int nt = 0; nt < 8; nt++) {
        int d = nt * 8 + dp;
        #pragma unroll
        for (int half = 0; half < 2; half++) {
            int s = srow0 + half * 8;
            size_t ix = ((size_t)s * BATCH + b) * EMB + h * HDIM + d;
            float2 uv = *(const float2*)&g_u[ix];
            float f0 = oacc[nt][half * 2]     * uv.x;
            float f1 = oacc[nt][half * 2 + 1] * uv.y;
            uint32_t hi, lo;
            split2(f0, f1, hi, lo);
            *(uint32_t*)((char*)g_gt_hi + ix * 2) = hi;
            *(uint32_t*)((char*)g_gt_lo + ix * 2) = lo;
        }
    }
}

// ---------------------------------------------------------------------------
extern "C" void kernel_launch(void* const* d_in, const int* in_sizes, int n_in,
                              void* d_out, int out_size) {
    const float* src   = (const float*)d_in[0];
    // d_in[1] = src_mask (causal tril) — predicate computed directly
    const float* in_w  = (const float*)d_in[2];
    const float* in_b  = (const float*)d_in[3];
    const float* out_w = (const float*)d_in[4];
    const float* out_b = (const float*)d_in[5];
    const float* ln_g  = (const float*)d_in[6];
    const float* ln_b  = (const float*)d_in[7];
    float* out = (float*)d_out;

    cudaFuncSetAttribute(attn_kernel, cudaFuncAttributeMaxDynamicSharedMemorySize, ATT_SMEM);
    cudaFuncSetAttribute(gemm_mma_kernel<0>, cudaFuncAttributeMaxDynamicSharedMemorySize, GEMM_SMEM);
    cudaFuncSetAttribute(gemm_mma_kernel<1>, cudaFuncAttributeMaxDynamicSharedMemorySize, GEMM_SMEM);

    ln_kernel<<<ROWS, 256>>>(src, ln_g, ln_b);
    wconv_kernel<<<3072, 256>>>(in_w, out_w);
    gemm_mma_kernel<0><<<dim3(2 * EMB / 128, ROWS / 128), 256, GEMM_SMEM>>>(
        in_b, nullptr, nullptr);
    attn_kernel<<<dim3(BATCH * HEADS, SEQ / 128), 256, ATT_SMEM>>>();
    gemm_mma_kernel<1><<<dim3(EMB / 128, ROWS / 128), 256, GEMM_SMEM>>>(
        out_b, src, out);
}

// round 15
// speedup vs baseline: 3.2463x; 1.1177x over previous
#include <cuda_runtime.h>
#include <cuda_fp16.h>
#include <math.h>
#include <stdint.h>

// Problem constants
#define SEQ 2048
#define BATCH 2
#define EMB 1024
#define HEADS 16
#define HDIM 64
#define ROWS (SEQ * BATCH)   // 4096

// ---------------------------------------------------------------------------
// Scratch (__device__ globals: allocation-free rule). fp16 split.
// Weights: HI ONLY (2-pass projections). Activations: hi+lo.
// ---------------------------------------------------------------------------
__device__ __align__(16) __half g_xn_hi[(size_t)ROWS * EMB];
__device__ __align__(16) __half g_xn_lo[(size_t)ROWS * EMB];
__device__ __align__(16) __half g_inw_h[(size_t)2 * EMB * EMB];
__device__ __align__(16) __half g_ow_h[(size_t)EMB * EMB];
__device__ __align__(16) __half g_gt_hi[(size_t)ROWS * EMB];
__device__ __align__(16) __half g_gt_lo[(size_t)ROWS * EMB];
// qkv split-fp16, row-major [s*B+b][E] (d-contiguous per head: col h*64+d)
__device__ __align__(16) __half g_k_hi[(size_t)ROWS * EMB];
__device__ __align__(16) __half g_k_lo[(size_t)ROWS * EMB];
__device__ float g_u[(size_t)ROWS * EMB];

// fast silu: MUFU.EX2 + fast divide (2-ulp class; error << split residual)
__device__ __forceinline__ float silu_f(float x) {
    return __fdividef(x, 1.0f + __expf(-x));
}

__device__ __forceinline__ uint32_t smem_u32(const void* p) {
    uint32_t a;
    asm("{ .reg .u64 t; cvta.to.shared.u64 t, %1; cvt.u32.u64 %0, t; }" : "=r"(a) : "l"(p));
    return a;
}

// Portable async-copy / ldmatrix / mma (compute_103-safe, sm_80+ ISA)
#define CP16(dst_u32, src_gptr) \
    asm volatile("cp.async.cg.shared.global [%0], [%1], 16;" \
                 :: "r"(dst_u32), "l"(__cvta_generic_to_global(src_gptr)) : "memory")
#define CP_COMMIT() asm volatile("cp.async.commit_group;" ::: "memory")
#define CP_WAIT(N)  asm volatile("cp.async.wait_group %0;" :: "n"(N) : "memory")

__device__ __forceinline__ void ldsm4(uint32_t* r, uint32_t addr) {
    asm volatile("ldmatrix.sync.aligned.m8n8.x4.shared.b16 {%0,%1,%2,%3}, [%4];"
                 : "=r"(r[0]), "=r"(r[1]), "=r"(r[2]), "=r"(r[3]) : "r"(addr));
}
__device__ __forceinline__ void ldsm4t(uint32_t* r, uint32_t addr) {
    asm volatile("ldmatrix.sync.aligned.m8n8.x4.trans.shared.b16 {%0,%1,%2,%3}, [%4];"
                 : "=r"(r[0]), "=r"(r[1]), "=r"(r[2]), "=r"(r[3]) : "r"(addr));
}
// fp16 mma, fp32 accumulate
__device__ __forceinline__ void mma16816(float* c, const uint32_t* a,
                                         uint32_t b0, uint32_t b1) {
    asm volatile(
        "mma.sync.aligned.m16n8k16.row.col.f32.f16.f16.f32 "
        "{%0,%1,%2,%3}, {%4,%5,%6,%7}, {%8,%9}, {%0,%1,%2,%3};"
        : "+f"(c[0]), "+f"(c[1]), "+f"(c[2]), "+f"(c[3])
        : "r"(a[0]), "r"(a[1]), "r"(a[2]), "r"(a[3]), "r"(b0), "r"(b1));
}

__device__ __forceinline__ void split_h(float v, __half& hi, __half& lo) {
    hi = __float2half(v);
    lo = __float2half(v - __half2float(hi));
}
// split two floats -> packed hi pair + lo pair (half2 as uint32)
__device__ __forceinline__ void split2(float f0, float f1, uint32_t& hi, uint32_t& lo) {
    __half h0 = __float2half(f0);
    __half h1 = __float2half(f1);
    __half l0 = __float2half(f0 - __half2float(h0));
    __half l1 = __float2half(f1 - __half2float(h1));
    __half2 H = __halves2half2(h0, h1);
    __half2 L = __halves2half2(l0, l1);
    hi = *reinterpret_cast<uint32_t*>(&H);
    lo = *reinterpret_cast<uint32_t*>(&L);
}

// ---------------------------------------------------------------------------
// Kernel 1: LayerNorm -> split-fp16 xnorm. One block (256 thr) per row.
// ---------------------------------------------------------------------------
__global__ void ln_kernel(const float* __restrict__ src,
                          const float* __restrict__ gamma,
                          const float* __restrict__ beta) {
    int row = blockIdx.x;
    int t = threadIdx.x;
    const float4* x4 = (const float4*)(src + (size_t)row * EMB);
    float4 v = x4[t];
    float s = v.x + v.y + v.z + v.w;
    float q = v.x * v.x + v.y * v.y + v.z * v.z + v.w * v.w;
    #pragma unroll
    for (int o = 16; o > 0; o >>= 1) {
        s += __shfl_xor_sync(0xFFFFFFFFu, s, o);
        q += __shfl_xor_sync(0xFFFFFFFFu, q, o);
    }
    __shared__ float ss[8], sq[8];
    int w = t >> 5, l = t & 31;
    if (l == 0) { ss[w] = s; sq[w] = q; }
    __syncthreads();
    float st = 0.f, qt = 0.f;
    #pragma unroll
    for (int i = 0; i < 8; i++) { st += ss[i]; qt += sq[i]; }
    float mu = st * (1.0f / EMB);
    float var = qt * (1.0f / EMB) - mu * mu;
    float inv = rsqrtf(var + 1e-5f);
    float4 gg = ((const float4*)gamma)[t];
    float4 bb = ((const float4*)beta)[t];
    float o[4];
    o[0] = (v.x - mu) * inv * gg.x + bb.x;
    o[1] = (v.y - mu) * inv * gg.y + bb.y;
    o[2] = (v.z - mu) * inv * gg.z + bb.z;
    o[3] = (v.w - mu) * inv * gg.w + bb.w;
    size_t base = (size_t)row * EMB + t * 4;
    #pragma unroll
    for (int e = 0; e < 4; e++) {
        __half hi, lo;
        split_h(o[e], hi, lo);
        g_xn_hi[base + e] = hi;
        g_xn_lo[base + e] = lo;
    }
}

// ---------------------------------------------------------------------------
// Kernel 2: convert in_proj_w + out_proj_w fp32 -> fp16 (hi only; 2-pass GEMM)
// ---------------------------------------------------------------------------
__global__ void wconv_kernel(const float* __restrict__ inw,
                             const float* __restrict__ outw) {
    const size_t N1 = (size_t)2 * EMB * EMB / 4;
    const size_t N2 = (size_t)EMB * EMB / 4;
    size_t i = (size_t)blockIdx.x * blockDim.x + threadIdx.x;
    if (i < N1) {
        float4 v = ((const float4*)inw)[i];
        __half2 p0 = __halves2half2(__float2half(v.x), __float2half(v.y));
        __half2 p1 = __halves2half2(__float2half(v.z), __float2half(v.w));
        *(__half2*)&g_inw_h[i * 4]     = p0;
        *(__half2*)&g_inw_h[i * 4 + 2] = p1;
    } else if (i < N1 + N2) {
        size_t j = i - N1;
        float4 v = ((const float4*)outw)[j];
        __half2 p0 = __halves2half2(__float2half(v.x), __float2half(v.y));
        __half2 p1 = __halves2half2(__float2half(v.z), __float2half(v.w));
        *(__half2*)&g_ow_h[j * 4]     = p0;
        *(__half2*)&g_ow_h[j * 4 + 2] = p1;
    }
}

// ---------------------------------------------------------------------------
// Split-fp16 2-pass GEMM via mma.sync:  C = (Ahi+Alo) @ Bhi^T
// Block 128x128, BK=32, 8 warps (warp tile 32x64), 3-stage cp.async pipeline.
// Stage = Ahi | Alo | Bhi (24 KB). 2 CTAs/SM.
// MODE 0 = in_proj (bias+silu -> qkv split-fp16 row-major / u fp32)
// MODE 1 = out_proj (src+bias -> out)
// ---------------------------------------------------------------------------
#define BK 32
#define NKS (EMB / BK)          // 32
#define STG_BYTES 24576
#define SUB_A_HI 0
#define SUB_A_LO 8192
#define SUB_B_HI 16384
#define GEMM_SMEM (3 * STG_BYTES)   // 73728

__device__ __forceinline__ void stage_load(uint32_t sdst,
                                           const __half* __restrict__ Ahi,
                                           const __half* __restrict__ Alo,
                                           const __half* __restrict__ Bhi,
                                           int bm, int bn, int k0, int tid) {
    #pragma unroll
    for (int t = 0; t < 2; t++) {
        int idx = tid + t * 256;            // 0..511
        int row = idx >> 2, seg = idx & 3;  // 128 rows x 4 x 16B
        uint32_t soff = row * 64 + ((seg ^ ((row >> 1) & 3)) << 4);
        size_t ga = (size_t)(bm + row) * EMB + k0 + seg * 8;
        size_t gb = (size_t)(bn + row) * EMB + k0 + seg * 8;
        CP16(sdst + SUB_A_HI + soff, Ahi + ga);
        CP16(sdst + SUB_A_LO + soff, Alo + ga);
        CP16(sdst + SUB_B_HI + soff, Bhi + gb);
    }
}

template <int MODE>
__global__ __launch_bounds__(256, 2)
void gemm_mma_kernel(const float* __restrict__ bias,
                     const float* __restrict__ src,
                     float* __restrict__ out) {
    extern __shared__ char smem[];
    uint32_t sb = smem_u32(smem);
    int tid = threadIdx.x, warp = tid >> 5, lane = tid & 31;
    int bn = blockIdx.x * 128, bm = blockIdx.y * 128;

    const __half *Ahi, *Alo, *Bhi;
    if (MODE == 0) { Ahi = g_xn_hi; Alo = g_xn_lo; Bhi = g_inw_h; }
    else           { Ahi = g_gt_hi; Alo = g_gt_lo; Bhi = g_ow_h; }

    // prologue: stages 0,1
    #pragma unroll
    for (int s = 0; s < 2; s++) {
        stage_load(sb + s * STG_BYTES, Ahi, Alo, Bhi, bm, bn, s * BK, tid);
        CP_COMMIT();
    }

    int wm = (warp >> 1) * 32;
    int wn = (warp & 1) * 64;
    int lrow = lane & 15;
    int lseg = lane >> 4;

    float acc[2][8][4];
    #pragma unroll
    for (int a = 0; a < 2; a++)
        #pragma unroll
        for (int b = 0; b < 8; b++)
            #pragma unroll
            for (int c = 0; c < 4; c++) acc[a][b][c] = 0.f;

    int buf = 0;
    for (int kt = 0; kt < NKS; kt++) {
        CP_WAIT(1);
        __syncthreads();
        uint32_t st = sb + (uint32_t)buf * STG_BYTES;
        if (kt + 2 < NKS) {
            int nbuf = buf + 2; if (nbuf >= 3) nbuf -= 3;
            stage_load(sb + (uint32_t)nbuf * STG_BYTES, Ahi, Alo, Bhi,
                       bm, bn, (kt + 2) * BK, tid);
            CP_COMMIT();
        }
        if (++buf == 3) buf = 0;
        #pragma unroll
        for (int kk = 0; kk < 2; kk++) {
            int seg = kk * 2 + lseg;
            uint32_t ahi[2][4], alo[2][4];
            #pragma unroll
            for (int mt = 0; mt < 2; mt++) {
                int r = wm + mt * 16 + lrow;
                uint32_t off = r * 64 + ((seg ^ ((r >> 1) & 3)) << 4);
                ldsm4(ahi[mt], st + SUB_A_HI + off);
                ldsm4(alo[mt], st + SUB_A_LO + off);
            }
            #pragma unroll
            for (int p = 0; p < 4; p++) {
                int r = wn + p * 16 + lrow;
                uint32_t off = r * 64 + ((seg ^ ((r >> 1) & 3)) << 4);
                uint32_t bhi[4];
                ldsm4(bhi, st + SUB_B_HI + off);
                #pragma unroll
                for (int mt = 0; mt < 2; mt++) {
                    mma16816(acc[mt][2 * p],     ahi[mt], bhi[0], bhi[2]);
                    mma16816(acc[mt][2 * p],     alo[mt], bhi[0], bhi[2]);
                    mma16816(acc[mt][2 * p + 1], ahi[mt], bhi[1], bhi[3]);
                    mma16816(acc[mt][2 * p + 1], alo[mt], bhi[1], bhi[3]);
                }
            }
        }
    }

    int r0 = bm + wm + (lane >> 2);
    int c0 = bn + wn + 2 * (lane & 3);
    #pragma unroll
    for (int mt = 0; mt < 2; mt++) {
        #pragma unroll
        for (int nt = 0; nt < 8; nt++) {
            int col = c0 + nt * 8;
            float* a = acc[mt][nt];
            int r = r0 + mt * 16;
            if (MODE == 0) {
                float b0 = bias[col], b1 = bias[col + 1];
                float v0 = silu_f(a[0] + b0);
                float v1 = silu_f(a[1] + b1);
                float v2 = silu_f(a[2] + b0);
                float v3 = silu_f(a[3] + b1);
                if (bn < EMB) {
                    // qkv half -> split-fp16, row-major (coalesced pair stores)
                    uint32_t hi, lo;
                    split2(v0, v1, hi, lo);
                    *(uint32_t*)((char*)g_k_hi + ((size_t)r * EMB + col) * 2) = hi;
                    *(uint32_t*)((char*)g_k_lo + ((size_t)r * EMB + col) * 2) = lo;
                    split2(v2, v3, hi, lo);
                    *(uint32_t*)((char*)g_k_hi + ((size_t)(r + 8) * EMB + col) * 2) = hi;
                    *(uint32_t*)((char*)g_k_lo + ((size_t)(r + 8) * EMB + col) * 2) = lo;
                } else {
                    int cc = col - EMB;
                    *(float2*)&g_u[(size_t)r * EMB + cc]       = make_float2(v0, v1);
                    *(float2*)&g_u[(size_t)(r + 8) * EMB + cc] = make_float2(v2, v3);
                }
            } else {
                float b0 = bias[col], b1 = bias[col + 1];
                float2 s0 = *(const float2*)&src[(size_t)r * EMB + col];
                float2 s1 = *(const float2*)&src[(size_t)(r + 8) * EMB + col];
                *(float2*)&out[(size_t)r * EMB + col] =
                    make_float2(s0.x + a[0] + b0, s0.y + a[1] + b1);
                *(float2*)&out[(size_t)(r + 8) * EMB + col] =
                    make_float2(s1.x + a[2] + b0, s1.y + a[3] + b1);
            }
        }
    }
}

// ---------------------------------------------------------------------------
// Kernel 3: tensor-core causal SiLU-attention (fp16 2-pass), fused gating.
// Scores = (Qhi+Qlo)@Khi^T ; PV: O += (Whi+Wlo)@Vhi  (K/V tiles hi-only).
// Block = 128 q-rows x one (b,h). 8 warps, warp = 16 q-rows.
// 4-stage hi-only K pipeline (8 KB/stage), 2 CTAs/SM, 64 KB smem.
// ---------------------------------------------------------------------------
#define ATT_SM_Q 0            // Qhi 16K @0 | Qlo 16K @16384
#define ATT_SM_K 32768        // 4 stages x (Khi 8K)
#define ATT_KSTG 8192
#define ATT_SMEM (32768 + 4 * ATT_KSTG)   // 65536

__device__ __forceinline__ void att_load_k(uint32_t sdst, int k0, int b, int h, int tid) {
    #pragma unroll
    for (int t = 0; t < 2; t++) {
        int idx = tid + t * 256;            // 0..511 -> 64 rows x 8 segs
        int row = idx >> 3, seg = idx & 7;
        uint32_t soff = row * 128 + ((seg ^ (row & 7)) << 4);
        size_t g = ((size_t)(k0 + row) * BATCH + b) * EMB + h * HDIM + seg * 8;
        CP16(sdst + soff, g_k_hi + g);
    }
}

__global__ __launch_bounds__(256, 2) void attn_kernel() {
    extern __shared__ char smem[];
    uint32_t sb = smem_u32(smem);
    int tid = threadIdx.x, warp = tid >> 5, lane = tid & 31;
    int kvb = blockIdx.x;                 // 0..31 = b*16 + h
    int qb = (gridDim.y - 1) - blockIdx.y; // long (diagonal) blocks launch first
    int b = kvb >> 4, h = kvb & 15;

    int L = 2 * qb + 1;       // last k-tile index (inclusive)

    // Prologue: Q hi+lo (128 rows) + K0 -> group0; K1 -> group1; K2 -> group2
    #pragma unroll
    for (int t = 0; t < 4; t++) {
        int idx = tid + t * 256;            // 0..1023 -> 128 rows x 8 segs
        int row = idx >> 3, seg = idx & 7;
        uint32_t soff = row * 128 + ((seg ^ (row & 7)) << 4);
        size_t g = ((size_t)(qb * 128 + row) * BATCH + b) * EMB + h * HDIM + seg * 8;
        CP16(sb + ATT_SM_Q + soff, g_k_hi + g);
        CP16(sb + ATT_SM_Q + 16384 + soff, g_k_lo + g);
    }
    att_load_k(sb + ATT_SM_K, 0, b, h, tid);
    CP_COMMIT();
    if (1 <= L) att_load_k(sb + ATT_SM_K + ATT_KSTG, 64, b, h, tid);
    CP_COMMIT();
    if (2 <= L) att_load_k(sb + ATT_SM_K + 2 * ATT_KSTG, 128, b, h, tid);
    CP_COMMIT();

    float oacc[8][4];
    #pragma unroll
    for (int i = 0; i < 8; i++)
        #pragma unroll
        for (int c = 0; c < 4; c++) oacc[i][c] = 0.f;

    for (int kt = 0; kt <= L; kt++) {
        CP_WAIT(2);
        __syncthreads();   // all warps done with tile kt-1; stage kt's data visible
        if (kt + 3 <= L)
            att_load_k(sb + ATT_SM_K + (uint32_t)((kt + 3) & 3) * ATT_KSTG,
                       (kt + 3) * 64, b, h, tid);
        CP_COMMIT();

        uint32_t sK = sb + ATT_SM_K + (uint32_t)(kt & 3) * ATT_KSTG;
        bool active = (kt * 64 <= qb * 128 + warp * 16 + 15);
        if (active) {
            // ---- scores: S = (Qhi+Qlo) @ Khi^T (2-pass) ----
            float sacc[8][4];
            #pragma unroll
            for (int i = 0; i < 8; i++)
                #pragma unroll
                for (int c = 0; c < 4; c++) sacc[i][c] = 0.f;
            #pragma unroll
            for (int ks = 0; ks < 4; ks++) {
                int rq = warp * 16 + (lane & 15);
                uint32_t qoff = rq * 128 + (((ks * 2 + (lane >> 4)) ^ (rq & 7)) << 4);
                uint32_t qh[4], ql[4];
                ldsm4(qh, sb + ATT_SM_Q + qoff);
                ldsm4(ql, sb + ATT_SM_Q + 16384 + qoff);
                #pragma unroll
                for (int p = 0; p < 4; p++) {
                    int r = p * 16 + (lane & 15);
                    uint32_t off = r * 128 + (((ks * 2 + (lane >> 4)) ^ (r & 7)) << 4);
                    uint32_t kh[4];
                    ldsm4(kh, sK + off);
                    mma16816(sacc[2 * p],     qh, kh[0], kh[2]);
                    mma16816(sacc[2 * p],     ql, kh[0], kh[2]);
                    mma16816(sacc[2 * p + 1], qh, kh[1], kh[3]);
                    mma16816(sacc[2 * p + 1], ql, kh[1], kh[3]);
                }
            }
            // ---- scale + silu + causal mask ----
            bool need_mask = (kt * 64 + 63 > qb * 128 + warp * 16);
            int qrow0 = qb * 128 + warp * 16 + (lane >> 2);
            #pragma unroll
            for (int nt = 0; nt < 8; nt++) {
                int kcol0 = kt * 64 + nt * 8 + 2 * (lane & 3);
                #pragma unroll
                for (int c = 0; c < 4; c++) {
                    float w = silu_f(sacc[nt][c] * 0.125f);
                    if (need_mask) {
                        int q = qrow0 + ((c >= 2) ? 8 : 0);
                        int k = kcol0 + (c & 1);
                        if (k > q) w = 0.f;
                    }
                    sacc[nt][c] = w;
                }
            }
            // ---- W -> A-frags (hi/lo) for PV ----
            uint32_t ahi[4][4], alo[4][4];
            #pragma unroll
            for (int ks = 0; ks < 4; ks++) {
                split2(sacc[2 * ks][0],     sacc[2 * ks][1],     ahi[ks][0], alo[ks][0]);
                split2(sacc[2 * ks][2],     sacc[2 * ks][3],     ahi[ks][1], alo[ks][1]);
                split2(sacc[2 * ks + 1][0], sacc[2 * ks + 1][1], ahi[ks][2], alo[ks][2]);
                split2(sacc[2 * ks + 1][2], sacc[2 * ks + 1][3], ahi[ks][3], alo[ks][3]);
            }
            // ---- O += (Whi+Wlo) @ Vhi (V == K tile, trans-ldmatrix; 2-pass) ----
            #pragma unroll
            for (int ks = 0; ks < 4; ks++) {
                #pragma unroll
                for (int p = 0; p < 4; p++) {
                    int r = ks * 16 + (lane & 15);
                    uint32_t off = r * 128 + (((p * 2 + (lane >> 4)) ^ (r & 7)) << 4);
                    uint32_t vh[4];
                    ldsm4t(vh, sK + off);
                    mma16816(oacc[2 * p],     ahi[ks], vh[0], vh[1]);
                    mma16816(oacc[2 * p],     alo[ks], vh[0], vh[1]);
                    mma16816(oacc[2 * p + 1], ahi[ks], vh[2], vh[3]);
                    mma16816(oacc[2 * p + 1], alo[ks], vh[2], vh[3]);
                }
            }
        }
    }

    // ---- Epilogue: gated = O * u -> split-fp16 for out_proj A ----
    int srow0 = qb * 128 + warp * 16 + (lane >> 2);
    int dp = 2 * (lane & 3);
    #pragma unroll
    for (int nt = 0; nt < 8; nt++) {
        int d = nt * 8 + dp;
        #pragma unroll
        for (int half = 0; half < 2; half++) {
            int s = srow0 + half * 8;
            size_t ix = ((size_t)s * BATCH + b) * EMB + h * HDIM + d;
            float2 uv = *(const float2*)&g_u[ix];
            float f0 = oacc[nt][half * 2]     * uv.x;
            float f1 = oacc[nt][half * 2 + 1] * uv.y;
            uint32_t hi, lo;
            split2(f0, f1, hi, lo);
            *(uint32_t*)((char*)g_gt_hi + ix * 2) = hi;
            *(uint32_t*)((char*)g_gt_lo + ix * 2) = lo;
        }
    }
}

// ---------------------------------------------------------------------------
extern "C" void kernel_launch(void* const* d_in, const int* in_sizes, int n_in,
                              void* d_out, int out_size) {
    const float* src   = (const float*)d_in[0];
    // d_in[1] = src_mask (causal tril) — predicate computed directly
    const float* in_w  = (const float*)d_in[2];
    const float* in_b  = (const float*)d_in[3];
    const float* out_w = (const float*)d_in[4];
    const float* out_b = (const float*)d_in[5];
    const float* ln_g  = (const float*)d_in[6];
    const float* ln_b  = (const float*)d_in[7];
    float* out = (float*)d_out;

    cudaFuncSetAttribute(attn_kernel, cudaFuncAttributeMaxDynamicSharedMemorySize, ATT_SMEM);
    cudaFuncSetAttribute(gemm_mma_kernel<0>, cudaFuncAttributeMaxDynamicSharedMemorySize, GEMM_SMEM);
    cudaFuncSetAttribute(gemm_mma_kernel<1>, cudaFuncAttributeMaxDynamicSharedMemorySize, GEMM_SMEM);

    ln_kernel<<<ROWS, 256>>>(src, ln_g, ln_b);
    wconv_kernel<<<3072, 256>>>(in_w, out_w);
    gemm_mma_kernel<0><<<dim3(2 * EMB / 128, ROWS / 128), 256, GEMM_SMEM>>>(
        in_b, nullptr, nullptr);
    attn_kernel<<<dim3(BATCH * HEADS, SEQ / 128), 256, ATT_SMEM>>>();
    gemm_mma_kernel<1><<<dim3(EMB / 128, ROWS / 128), 256, GEMM_SMEM>>>(
        out_b, src, out);
}

// round 16
// speedup vs baseline: 4.2626x; 1.3130x over previous
#include <cuda_runtime.h>
#include <cuda_fp16.h>
#include <math.h>
#include <stdint.h>

// Problem constants
#define SEQ 2048
#define BATCH 2
#define EMB 1024
#define HEADS 16
#define HDIM 64
#define ROWS (SEQ * BATCH)   // 4096

// ---------------------------------------------------------------------------
// Scratch (__device__ globals: allocation-free rule). fp16.
// Projections are 1-pass (hi-only both operands). Attention keeps qkv hi+lo.
// ---------------------------------------------------------------------------
__device__ __align__(16) __half g_xn_hi[(size_t)ROWS * EMB];
__device__ __align__(16) __half g_inw_h[(size_t)2 * EMB * EMB];
__device__ __align__(16) __half g_ow_h[(size_t)EMB * EMB];
__device__ __align__(16) __half g_gt_hi[(size_t)ROWS * EMB];
// qkv split-fp16, row-major [s*B+b][E] (d-contiguous per head: col h*64+d)
__device__ __align__(16) __half g_k_hi[(size_t)ROWS * EMB];
__device__ __align__(16) __half g_k_lo[(size_t)ROWS * EMB];
__device__ float g_u[(size_t)ROWS * EMB];

// fast silu: MUFU.EX2 + fast divide (2-ulp class; error << split residual)
__device__ __forceinline__ float silu_f(float x) {
    return __fdividef(x, 1.0f + __expf(-x));
}

__device__ __forceinline__ uint32_t smem_u32(const void* p) {
    uint32_t a;
    asm("{ .reg .u64 t; cvta.to.shared.u64 t, %1; cvt.u32.u64 %0, t; }" : "=r"(a) : "l"(p));
    return a;
}

// Portable async-copy / ldmatrix / mma (compute_103-safe, sm_80+ ISA)
#define CP16(dst_u32, src_gptr) \
    asm volatile("cp.async.cg.shared.global [%0], [%1], 16;" \
                 :: "r"(dst_u32), "l"(__cvta_generic_to_global(src_gptr)) : "memory")
#define CP_COMMIT() asm volatile("cp.async.commit_group;" ::: "memory")
#define CP_WAIT(N)  asm volatile("cp.async.wait_group %0;" :: "n"(N) : "memory")

__device__ __forceinline__ void ldsm4(uint32_t* r, uint32_t addr) {
    asm volatile("ldmatrix.sync.aligned.m8n8.x4.shared.b16 {%0,%1,%2,%3}, [%4];"
                 : "=r"(r[0]), "=r"(r[1]), "=r"(r[2]), "=r"(r[3]) : "r"(addr));
}
__device__ __forceinline__ void ldsm4t(uint32_t* r, uint32_t addr) {
    asm volatile("ldmatrix.sync.aligned.m8n8.x4.trans.shared.b16 {%0,%1,%2,%3}, [%4];"
                 : "=r"(r[0]), "=r"(r[1]), "=r"(r[2]), "=r"(r[3]) : "r"(addr));
}
// fp16 mma, fp32 accumulate
__device__ __forceinline__ void mma16816(float* c, const uint32_t* a,
                                         uint32_t b0, uint32_t b1) {
    asm volatile(
        "mma.sync.aligned.m16n8k16.row.col.f32.f16.f16.f32 "
        "{%0,%1,%2,%3}, {%4,%5,%6,%7}, {%8,%9}, {%0,%1,%2,%3};"
        : "+f"(c[0]), "+f"(c[1]), "+f"(c[2]), "+f"(c[3])
        : "r"(a[0]), "r"(a[1]), "r"(a[2]), "r"(a[3]), "r"(b0), "r"(b1));
}

// split two floats -> packed hi pair + lo pair (half2 as uint32)
__device__ __forceinline__ void split2(float f0, float f1, uint32_t& hi, uint32_t& lo) {
    __half h0 = __float2half(f0);
    __half h1 = __float2half(f1);
    __half l0 = __float2half(f0 - __half2float(h0));
    __half l1 = __float2half(f1 - __half2float(h1));
    __half2 H = __halves2half2(h0, h1);
    __half2 L = __halves2half2(l0, l1);
    hi = *reinterpret_cast<uint32_t*>(&H);
    lo = *reinterpret_cast<uint32_t*>(&L);
}
__device__ __forceinline__ uint32_t pack2(float f0, float f1) {
    __half2 H = __halves2half2(__float2half(f0), __float2half(f1));
    return *reinterpret_cast<uint32_t*>(&H);
}

// ---------------------------------------------------------------------------
// Kernel 1: LayerNorm -> fp16 xnorm (hi only; 1-pass in_proj).
// ---------------------------------------------------------------------------
__global__ void ln_kernel(const float* __restrict__ src,
                          const float* __restrict__ gamma,
                          const float* __restrict__ beta) {
    int row = blockIdx.x;
    int t = threadIdx.x;
    const float4* x4 = (const float4*)(src + (size_t)row * EMB);
    float4 v = x4[t];
    float s = v.x + v.y + v.z + v.w;
    float q = v.x * v.x + v.y * v.y + v.z * v.z + v.w * v.w;
    #pragma unroll
    for (int o = 16; o > 0; o >>= 1) {
        s += __shfl_xor_sync(0xFFFFFFFFu, s, o);
        q += __shfl_xor_sync(0xFFFFFFFFu, q, o);
    }
    __shared__ float ss[8], sq[8];
    int w = t >> 5, l = t & 31;
    if (l == 0) { ss[w] = s; sq[w] = q; }
    __syncthreads();
    float st = 0.f, qt = 0.f;
    #pragma unroll
    for (int i = 0; i < 8; i++) { st += ss[i]; qt += sq[i]; }
    float mu = st * (1.0f / EMB);
    float var = qt * (1.0f / EMB) - mu * mu;
    float inv = rsqrtf(var + 1e-5f);
    float4 gg = ((const float4*)gamma)[t];
    float4 bb = ((const float4*)beta)[t];
    float o0 = (v.x - mu) * inv * gg.x + bb.x;
    float o1 = (v.y - mu) * inv * gg.y + bb.y;
    float o2 = (v.z - mu) * inv * gg.z + bb.z;
    float o3 = (v.w - mu) * inv * gg.w + bb.w;
    size_t base = (size_t)row * EMB + t * 4;
    *(uint32_t*)&g_xn_hi[base]     = pack2(o0, o1);
    *(uint32_t*)&g_xn_hi[base + 2] = pack2(o2, o3);
}

// ---------------------------------------------------------------------------
// Kernel 2: convert in_proj_w + out_proj_w fp32 -> fp16 (hi only)
// ---------------------------------------------------------------------------
__global__ void wconv_kernel(const float* __restrict__ inw,
                             const float* __restrict__ outw) {
    const size_t N1 = (size_t)2 * EMB * EMB / 4;
    const size_t N2 = (size_t)EMB * EMB / 4;
    size_t i = (size_t)blockIdx.x * blockDim.x + threadIdx.x;
    if (i < N1) {
        float4 v = ((const float4*)inw)[i];
        *(uint32_t*)&g_inw_h[i * 4]     = pack2(v.x, v.y);
        *(uint32_t*)&g_inw_h[i * 4 + 2] = pack2(v.z, v.w);
    } else if (i < N1 + N2) {
        size_t j = i - N1;
        float4 v = ((const float4*)outw)[j];
        *(uint32_t*)&g_ow_h[j * 4]     = pack2(v.x, v.y);
        *(uint32_t*)&g_ow_h[j * 4 + 2] = pack2(v.z, v.w);
    }
}

// ---------------------------------------------------------------------------
// 1-pass fp16 GEMM via mma.sync:  C = Ahi @ Bhi^T
// Block 128x128, BK=32, 8 warps (warp tile 32x64), 3-stage cp.async pipeline.
// Stage = Ahi | Bhi (16 KB). 2 CTAs/SM.
// MODE 0 = in_proj (bias+silu -> qkv split-fp16 row-major / u fp32)
// MODE 1 = out_proj (src+bias -> out)
// ---------------------------------------------------------------------------
#define BK 32
#define NKS (EMB / BK)          // 32
#define STG_BYTES 16384
#define SUB_A 0
#define SUB_B 8192
#define GEMM_SMEM (3 * STG_BYTES)   // 49152

__device__ __forceinline__ void stage_load(uint32_t sdst,
                                           const __half* __restrict__ Ahi,
                                           const __half* __restrict__ Bhi,
                                           int bm, int bn, int k0, int tid) {
    #pragma unroll
    for (int t = 0; t < 2; t++) {
        int idx = tid + t * 256;            // 0..511
        int row = idx >> 2, seg = idx & 3;  // 128 rows x 4 x 16B
        uint32_t soff = row * 64 + ((seg ^ ((row >> 1) & 3)) << 4);
        size_t ga = (size_t)(bm + row) * EMB + k0 + seg * 8;
        size_t gb = (size_t)(bn + row) * EMB + k0 + seg * 8;
        CP16(sdst + SUB_A + soff, Ahi + ga);
        CP16(sdst + SUB_B + soff, Bhi + gb);
    }
}

template <int MODE>
__global__ __launch_bounds__(256, 2)
void gemm_mma_kernel(const float* __restrict__ bias,
                     const float* __restrict__ src,
                     float* __restrict__ out) {
    extern __shared__ char smem[];
    uint32_t sb = smem_u32(smem);
    int tid = threadIdx.x, warp = tid >> 5, lane = tid & 31;
    int bn = blockIdx.x * 128, bm = blockIdx.y * 128;

    const __half *Ahi, *Bhi;
    if (MODE == 0) { Ahi = g_xn_hi; Bhi = g_inw_h; }
    else           { Ahi = g_gt_hi; Bhi = g_ow_h; }

    // prologue: stages 0,1
    #pragma unroll
    for (int s = 0; s < 2; s++) {
        stage_load(sb + s * STG_BYTES, Ahi, Bhi, bm, bn, s * BK, tid);
        CP_COMMIT();
    }

    int wm = (warp >> 1) * 32;
    int wn = (warp & 1) * 64;
    int lrow = lane & 15;
    int lseg = lane >> 4;

    float acc[2][8][4];
    #pragma unroll
    for (int a = 0; a < 2; a++)
        #pragma unroll
        for (int b = 0; b < 8; b++)
            #pragma unroll
            for (int c = 0; c < 4; c++) acc[a][b][c] = 0.f;

    int buf = 0;
    for (int kt = 0; kt < NKS; kt++) {
        CP_WAIT(1);
        __syncthreads();
        uint32_t st = sb + (uint32_t)buf * STG_BYTES;
        if (kt + 2 < NKS) {
            int nbuf = buf + 2; if (nbuf >= 3) nbuf -= 3;
            stage_load(sb + (uint32_t)nbuf * STG_BYTES, Ahi, Bhi,
                       bm, bn, (kt + 2) * BK, tid);
            CP_COMMIT();
        }
        if (++buf == 3) buf = 0;
        #pragma unroll
        for (int kk = 0; kk < 2; kk++) {
            int seg = kk * 2 + lseg;
            uint32_t ahi[2][4];
            #pragma unroll
            for (int mt = 0; mt < 2; mt++) {
                int r = wm + mt * 16 + lrow;
                uint32_t off = r * 64 + ((seg ^ ((r >> 1) & 3)) << 4);
                ldsm4(ahi[mt], st + SUB_A + off);
            }
            #pragma unroll
            for (int p = 0; p < 4; p++) {
                int r = wn + p * 16 + lrow;
                uint32_t off = r * 64 + ((seg ^ ((r >> 1) & 3)) << 4);
                uint32_t bhi[4];
                ldsm4(bhi, st + SUB_B + off);
                #pragma unroll
                for (int mt = 0; mt < 2; mt++) {
                    mma16816(acc[mt][2 * p],     ahi[mt], bhi[0], bhi[2]);
                    mma16816(acc[mt][2 * p + 1], ahi[mt], bhi[1], bhi[3]);
                }
            }
        }
    }

    int r0 = bm + wm + (lane >> 2);
    int c0 = bn + wn + 2 * (lane & 3);
    #pragma unroll
    for (int mt = 0; mt < 2; mt++) {
        #pragma unroll
        for (int nt = 0; nt < 8; nt++) {
            int col = c0 + nt * 8;
            float* a = acc[mt][nt];
            int r = r0 + mt * 16;
            if (MODE == 0) {
                float b0 = bias[col], b1 = bias[col + 1];
                float v0 = silu_f(a[0] + b0);
                float v1 = silu_f(a[1] + b1);
                float v2 = silu_f(a[2] + b0);
                float v3 = silu_f(a[3] + b1);
                if (bn < EMB) {
                    // qkv half -> split-fp16, row-major (coalesced pair stores)
                    uint32_t hi, lo;
                    split2(v0, v1, hi, lo);
                    *(uint32_t*)((char*)g_k_hi + ((size_t)r * EMB + col) * 2) = hi;
                    *(uint32_t*)((char*)g_k_lo + ((size_t)r * EMB + col) * 2) = lo;
                    split2(v2, v3, hi, lo);
                    *(uint32_t*)((char*)g_k_hi + ((size_t)(r + 8) * EMB + col) * 2) = hi;
                    *(uint32_t*)((char*)g_k_lo + ((size_t)(r + 8) * EMB + col) * 2) = lo;
                } else {
                    int cc = col - EMB;
                    *(float2*)&g_u[(size_t)r * EMB + cc]       = make_float2(v0, v1);
                    *(float2*)&g_u[(size_t)(r + 8) * EMB + cc] = make_float2(v2, v3);
                }
            } else {
                float b0 = bias[col], b1 = bias[col + 1];
                float2 s0 = *(const float2*)&src[(size_t)r * EMB + col];
                float2 s1 = *(const float2*)&src[(size_t)(r + 8) * EMB + col];
                *(float2*)&out[(size_t)r * EMB + col] =
                    make_float2(s0.x + a[0] + b0, s0.y + a[1] + b1);
                *(float2*)&out[(size_t)(r + 8) * EMB + col] =
                    make_float2(s1.x + a[2] + b0, s1.y + a[3] + b1);
            }
        }
    }
}

// ---------------------------------------------------------------------------
// Kernel 3: tensor-core causal SiLU-attention (fp16 2-pass), fused gating.
// Scores = (Qhi+Qlo)@Khi^T ; PV: O += (Whi+Wlo)@Vhi  (K/V tiles hi-only).
// Block = 128 q-rows x one (b,h). 8 warps, warp = 16 q-rows.
// 4-stage hi-only K pipeline (8 KB/stage), 2 CTAs/SM, 64 KB smem.
// ---------------------------------------------------------------------------
#define ATT_SM_Q 0            // Qhi 16K @0 | Qlo 16K @16384
#define ATT_SM_K 32768        // 4 stages x (Khi 8K)
#define ATT_KSTG 8192
#define ATT_SMEM (32768 + 4 * ATT_KSTG)   // 65536

__device__ __forceinline__ void att_load_k(uint32_t sdst, int k0, int b, int h, int tid) {
    #pragma unroll
    for (int t = 0; t < 2; t++) {
        int idx = tid + t * 256;            // 0..511 -> 64 rows x 8 segs
        int row = idx >> 3, seg = idx & 7;
        uint32_t soff = row * 128 + ((seg ^ (row & 7)) << 4);
        size_t g = ((size_t)(k0 + row) * BATCH + b) * EMB + h * HDIM + seg * 8;
        CP16(sdst + soff, g_k_hi + g);
    }
}

__global__ __launch_bounds__(256, 2) void attn_kernel() {
    extern __shared__ char smem[];
    uint32_t sb = smem_u32(smem);
    int tid = threadIdx.x, warp = tid >> 5, lane = tid & 31;
    int kvb = blockIdx.x;                 // 0..31 = b*16 + h
    int qb = (gridDim.y - 1) - blockIdx.y; // long (diagonal) blocks launch first
    int b = kvb >> 4, h = kvb & 15;

    int L = 2 * qb + 1;       // last k-tile index (inclusive)

    // Prologue: Q hi+lo (128 rows) + K0 -> group0; K1 -> group1; K2 -> group2
    #pragma unroll
    for (int t = 0; t < 4; t++) {
        int idx = tid + t * 256;            // 0..1023 -> 128 rows x 8 segs
        int row = idx >> 3, seg = idx & 7;
        uint32_t soff = row * 128 + ((seg ^ (row & 7)) << 4);
        size_t g = ((size_t)(qb * 128 + row) * BATCH + b) * EMB + h * HDIM + seg * 8;
        CP16(sb + ATT_SM_Q + soff, g_k_hi + g);
        CP16(sb + ATT_SM_Q + 16384 + soff, g_k_lo + g);
    }
    att_load_k(sb + ATT_SM_K, 0, b, h, tid);
    CP_COMMIT();
    if (1 <= L) att_load_k(sb + ATT_SM_K + ATT_KSTG, 64, b, h, tid);
    CP_COMMIT();
    if (2 <= L) att_load_k(sb + ATT_SM_K + 2 * ATT_KSTG, 128, b, h, tid);
    CP_COMMIT();

    float oacc[8][4];
    #pragma unroll
    for (int i = 0; i < 8; i++)
        #pragma unroll
        for (int c = 0; c < 4; c++) oacc[i][c] = 0.f;

    for (int kt = 0; kt <= L; kt++) {
        CP_WAIT(2);
        __syncthreads();   // all warps done with tile kt-1; stage kt's data visible
        if (kt + 3 <= L)
            att_load_k(sb + ATT_SM_K + (uint32_t)((kt + 3) & 3) * ATT_KSTG,
                       (kt + 3) * 64, b, h, tid);
        CP_COMMIT();

        uint32_t sK = sb + ATT_SM_K + (uint32_t)(kt & 3) * ATT_KSTG;
        bool active = (kt * 64 <= qb * 128 + warp * 16 + 15);
        if (active) {
            // ---- scores: S = (Qhi+Qlo) @ Khi^T (2-pass) ----
            float sacc[8][4];
            #pragma unroll
            for (int i = 0; i < 8; i++)
                #pragma unroll
                for (int c = 0; c < 4; c++) sacc[i][c] = 0.f;
            #pragma unroll
            for (int ks = 0; ks < 4; ks++) {
                int rq = warp * 16 + (lane & 15);
                uint32_t qoff = rq * 128 + (((ks * 2 + (lane >> 4)) ^ (rq & 7)) << 4);
                uint32_t qh[4], ql[4];
                ldsm4(qh, sb + ATT_SM_Q + qoff);
                ldsm4(ql, sb + ATT_SM_Q + 16384 + qoff);
                #pragma unroll
                for (int p = 0; p < 4; p++) {
                    int r = p * 16 + (lane & 15);
                    uint32_t off = r * 128 + (((ks * 2 + (lane >> 4)) ^ (r & 7)) << 4);
                    uint32_t kh[4];
                    ldsm4(kh, sK + off);
                    mma16816(sacc[2 * p],     qh, kh[0], kh[2]);
                    mma16816(sacc[2 * p],     ql, kh[0], kh[2]);
                    mma16816(sacc[2 * p + 1], qh, kh[1], kh[3]);
                    mma16816(sacc[2 * p + 1], ql, kh[1], kh[3]);
                }
            }
            // ---- scale + silu + causal mask ----
            bool need_mask = (kt * 64 + 63 > qb * 128 + warp * 16);
            int qrow0 = qb * 128 + warp * 16 + (lane >> 2);
            #pragma unroll
            for (int nt = 0; nt < 8; nt++) {
                int kcol0 = kt * 64 + nt * 8 + 2 * (lane & 3);
                #pragma unroll
                for (int c = 0; c < 4; c++) {
                    float w = silu_f(sacc[nt][c] * 0.125f);
                    if (need_mask) {
                        int q = qrow0 + ((c >= 2) ? 8 : 0);
                        int k = kcol0 + (c & 1);
                        if (k > q) w = 0.f;
                    }
                    sacc[nt][c] = w;
                }
            }
            // ---- W -> A-frags (hi/lo) for PV ----
            uint32_t ahi[4][4], alo[4][4];
            #pragma unroll
            for (int ks = 0; ks < 4; ks++) {
                split2(sacc[2 * ks][0],     sacc[2 * ks][1],     ahi[ks][0], alo[ks][0]);
                split2(sacc[2 * ks][2],     sacc[2 * ks][3],     ahi[ks][1], alo[ks][1]);
                split2(sacc[2 * ks + 1][0], sacc[2 * ks + 1][1], ahi[ks][2], alo[ks][2]);
                split2(sacc[2 * ks + 1][2], sacc[2 * ks + 1][3], ahi[ks][3], alo[ks][3]);
            }
            // ---- O += (Whi+Wlo) @ Vhi (V == K tile, trans-ldmatrix; 2-pass) ----
            #pragma unroll
            for (int ks = 0; ks < 4; ks++) {
                #pragma unroll
                for (int p = 0; p < 4; p++) {
                    int r = ks * 16 + (lane & 15);
                    uint32_t off = r * 128 + (((p * 2 + (lane >> 4)) ^ (r & 7)) << 4);
                    uint32_t vh[4];
                    ldsm4t(vh, sK + off);
                    mma16816(oacc[2 * p],     ahi[ks], vh[0], vh[1]);
                    mma16816(oacc[2 * p],     alo[ks], vh[0], vh[1]);
                    mma16816(oacc[2 * p + 1], ahi[ks], vh[2], vh[3]);
                    mma16816(oacc[2 * p + 1], alo[ks], vh[2], vh[3]);
                }
            }
        }
    }

    // ---- Epilogue: gated = O * u -> fp16 hi for 1-pass out_proj ----
    int srow0 = qb * 128 + warp * 16 + (lane >> 2);
    int dp = 2 * (lane & 3);
    #pragma unroll
    for (int nt = 0; nt < 8; nt++) {
        int d = nt * 8 + dp;
        #pragma unroll
        for (int half = 0; half < 2; half++) {
            int s = srow0 + half * 8;
            size_t ix = ((size_t)s * BATCH + b) * EMB + h * HDIM + d;
            float2 uv = *(const float2*)&g_u[ix];
            float f0 = oacc[nt][half * 2]     * uv.x;
            float f1 = oacc[nt][half * 2 + 1] * uv.y;
            *(uint32_t*)((char*)g_gt_hi + ix * 2) = pack2(f0, f1);
        }
    }
}

// ---------------------------------------------------------------------------
extern "C" void kernel_launch(void* const* d_in, const int* in_sizes, int n_in,
                              void* d_out, int out_size) {
    const float* src   = (const float*)d_in[0];
    // d_in[1] = src_mask (causal tril) — predicate computed directly
    const float* in_w  = (const float*)d_in[2];
    const float* in_b  = (const float*)d_in[3];
    const float* out_w = (const float*)d_in[4];
    const float* out_b = (const float*)d_in[5];
    const float* ln_g  = (const float*)d_in[6];
    const float* ln_b  = (const float*)d_in[7];
    float* out = (float*)d_out;

    cudaFuncSetAttribute(attn_kernel, cudaFuncAttributeMaxDynamicSharedMemorySize, ATT_SMEM);
    cudaFuncSetAttribute(gemm_mma_kernel<0>, cudaFuncAttributeMaxDynamicSharedMemorySize, GEMM_SMEM);
    cudaFuncSetAttribute(gemm_mma_kernel<1>, cudaFuncAttributeMaxDynamicSharedMemorySize, GEMM_SMEM);

    ln_kernel<<<ROWS, 256>>>(src, ln_g, ln_b);
    wconv_kernel<<<3072, 256>>>(in_w, out_w);
    gemm_mma_kernel<0><<<dim3(2 * EMB / 128, ROWS / 128), 256, GEMM_SMEM>>>(
        in_b, nullptr, nullptr);
    attn_kernel<<<dim3(BATCH * HEADS, SEQ / 128), 256, ATT_SMEM>>>();
    gemm_mma_kernel<1><<<dim3(EMB / 128, ROWS / 128), 256, GEMM_SMEM>>>(
        out_b, src, out);
}